// round 3
// baseline (speedup 1.0000x reference)
#include <cuda_runtime.h>
#include <cstdint>

#define T_LEN 2048
#define B_SZ  2
#define EMB   512
#define ROWS  4096       // B*T
#define HEADS 8
#define HDIM  64
#define NHASH 2
#define FULLMASK 0xffffffffu

// ---------------------------------------------------------------------------
// Scratch (no cudaMalloc allowed -> __device__ globals)
// ---------------------------------------------------------------------------
__device__ float g_Q[ROWS * EMB];
__device__ float g_K[ROWS * EMB];
__device__ float g_V[ROWS * EMB];
__device__ unsigned char g_qh[NHASH * B_SZ * HEADS * T_LEN];
__device__ unsigned char g_kh[NHASH * B_SZ * HEADS * T_LEN];
__device__ float g_att[NHASH][ROWS * EMB];

// ---------------------------------------------------------------------------
// Kernel 1: fused QKV projection.
// C[f][e] = sum_k X[src(f)][k] * W[e][k] + bias[e], src(f) = (f&1)*T + (f>>1)
// (this bakes in the reference's swapaxes+reshape index identity).
// 128x128 block tile, BK=16, 256 threads, 8x8 per thread.
// ---------------------------------------------------------------------------
__global__ __launch_bounds__(256) void gemm_proj(const float* __restrict__ X,
                                                 const float* __restrict__ W,
                                                 const float* __restrict__ bias,
                                                 int which)
{
    __shared__ float As[16][132];
    __shared__ float Bs[16][132];
    const int tid = threadIdx.x;
    const int bn = blockIdx.x;   // 0..3   (N=512)
    const int bm = blockIdx.y;   // 0..31  (M=4096)
    const int tx = tid & 15, ty = tid >> 4;

    float acc[8][8];
#pragma unroll
    for (int i = 0; i < 8; i++)
#pragma unroll
        for (int j = 0; j < 8; j++) acc[i][j] = 0.f;

    for (int kk = 0; kk < EMB; kk += 16) {
#pragma unroll
        for (int i = 0; i < 2; i++) {
            int idx = tid * 2 + i;          // 0..511
            int rr  = idx >> 2;             // 0..127 (row/e in tile)
            int k4  = idx & 3;              // float4 slot along k
            int r   = bm * 128 + rr;
            int src = (r & 1) * T_LEN + (r >> 1);
            float4 a = *reinterpret_cast<const float4*>(X + (size_t)src * EMB + kk + k4 * 4);
            As[k4 * 4 + 0][rr] = a.x; As[k4 * 4 + 1][rr] = a.y;
            As[k4 * 4 + 2][rr] = a.z; As[k4 * 4 + 3][rr] = a.w;
            float4 b = *reinterpret_cast<const float4*>(W + (size_t)(bn * 128 + rr) * EMB + kk + k4 * 4);
            Bs[k4 * 4 + 0][rr] = b.x; Bs[k4 * 4 + 1][rr] = b.y;
            Bs[k4 * 4 + 2][rr] = b.z; Bs[k4 * 4 + 3][rr] = b.w;
        }
        __syncthreads();
#pragma unroll
        for (int k = 0; k < 16; k++) {
            float av[8], bv[8];
#pragma unroll
            for (int i = 0; i < 8; i++) av[i] = As[k][ty * 8 + i];
#pragma unroll
            for (int j = 0; j < 8; j++) bv[j] = Bs[k][tx * 8 + j];
#pragma unroll
            for (int i = 0; i < 8; i++)
#pragma unroll
                for (int j = 0; j < 8; j++) acc[i][j] += av[i] * bv[j];
        }
        __syncthreads();
    }

    float* outp = (which == 0) ? g_Q : (which == 1) ? g_K : g_V;
    float bb[8];
#pragma unroll
    for (int j = 0; j < 8; j++) bb[j] = bias[bn * 128 + tx * 8 + j];
#pragma unroll
    for (int i = 0; i < 8; i++) {
        int r = bm * 128 + ty * 8 + i;
        float* op = outp + (size_t)r * EMB + bn * 128 + tx * 8;
#pragma unroll
        for (int j4 = 0; j4 < 8; j4 += 4) {
            float4 v;
            v.x = acc[i][j4 + 0] + bb[j4 + 0];
            v.y = acc[i][j4 + 1] + bb[j4 + 1];
            v.z = acc[i][j4 + 2] + bb[j4 + 2];
            v.w = acc[i][j4 + 3] + bb[j4 + 3];
            *reinterpret_cast<float4*>(op + j4) = v;
        }
    }
}

// ---------------------------------------------------------------------------
// Kernel 2: LSH bucket ids.
// bucket(row,h,hash) = argmax_d ( v . lshW[hash][d][:] + lshb[hash][d] )
// grid.y: 0 -> hash Q into g_qh, 1 -> hash K into g_kh.
// One warp per (row, head), both hashes.
// ---------------------------------------------------------------------------
__global__ __launch_bounds__(256) void hash_kernel(const float* __restrict__ lshW,
                                                   const float* __restrict__ lshb)
{
    __shared__ float Ws[2][64][65];
    __shared__ float bs[2][64];
    __shared__ float vsh[8][64];
    const int tid = threadIdx.x;

    for (int i = tid; i < 2 * 64 * 64; i += 256) {
        int hh = i >> 12, d = (i >> 6) & 63, j = i & 63;
        Ws[hh][d][j] = lshW[i];
    }
    for (int i = tid; i < 128; i += 256) bs[i >> 6][i & 63] = lshb[i];
    __syncthreads();

    const int warp = tid >> 5, lane = tid & 31;
    const int task = blockIdx.x * 8 + warp;     // 0..32767
    const int row = task >> 3;                  // 0..4095
    const int h   = task & 7;

    const float* src = (blockIdx.y == 0) ? g_Q : g_K;
    unsigned char* dst = (blockIdx.y == 0) ? g_qh : g_kh;

    float2 v = *reinterpret_cast<const float2*>(src + (size_t)row * EMB + h * HDIM + lane * 2);
    vsh[warp][lane * 2] = v.x;
    vsh[warp][lane * 2 + 1] = v.y;
    __syncwarp();

    const int b = row >> 11;       // nb
    const int t = row & 2047;      // nt

#pragma unroll
    for (int hh = 0; hh < 2; hh++) {
        float s1 = bs[hh][lane];
        float s2 = bs[hh][lane + 32];
#pragma unroll
        for (int j = 0; j < 64; j++) {
            float q = vsh[warp][j];
            s1 += q * Ws[hh][lane][j];
            s2 += q * Ws[hh][lane + 32][j];
        }
        float bv; int bi;
        if (s2 > s1) { bv = s2; bi = lane + 32; } else { bv = s1; bi = lane; }
#pragma unroll
        for (int off = 16; off; off >>= 1) {
            float ov = __shfl_xor_sync(FULLMASK, bv, off);
            int   oi = __shfl_xor_sync(FULLMASK, bi, off);
            if (ov > bv || (ov == bv && oi < bi)) { bv = ov; bi = oi; }
        }
        if (lane == 0)
            dst[((hh * B_SZ + b) * HEADS + h) * T_LEN + t] = (unsigned char)bi;
    }
}

// ---------------------------------------------------------------------------
// Kernel 3: sparse bucketed attention with online softmax.
// grid = (T/64, B*H, NHASH); 8 warps/block, 8 queries per warp.
// Per query: ballot-scan kh for bucket matches, dot/softmax only on matches.
// Writes full 64-dim output per (hash, b, h, t) (zeros when invalid).
// ---------------------------------------------------------------------------
__global__ __launch_bounds__(256) void attn_kernel()
{
    __shared__ uint32_t khs4[T_LEN / 4];
    const unsigned char* khs = reinterpret_cast<const unsigned char*>(khs4);

    const int hash = blockIdx.z;
    const int bh = blockIdx.y;
    const int b = bh >> 3, h = bh & 7;
    const int tid = threadIdx.x;

    const unsigned char* khp = g_kh + ((size_t)(hash * B_SZ + b) * HEADS + h) * T_LEN;
    const unsigned char* qhp = g_qh + ((size_t)(hash * B_SZ + b) * HEADS + h) * T_LEN;
    for (int i = tid; i < T_LEN / 4; i += 256)
        khs4[i] = reinterpret_cast<const uint32_t*>(khp)[i];
    __syncthreads();

    const int warp = tid >> 5, lane = tid & 31;
    const float* Qp = g_Q + (size_t)b * T_LEN * EMB + h * HDIM;
    const float* Kp = g_K + (size_t)b * T_LEN * EMB + h * HDIM;
    const float* Vp = g_V + (size_t)b * T_LEN * EMB + h * HDIM;
    float* Op = g_att[hash] + (size_t)b * T_LEN * EMB + h * HDIM;

    for (int qi = 0; qi < 8; qi++) {
        const int t = blockIdx.x * 64 + warp * 8 + qi;
        const unsigned char qb = qhp[t];
        float o0 = 0.f, o1 = 0.f;

        if (qb < 32) {
            float2 q = *reinterpret_cast<const float2*>(Qp + (size_t)t * EMB + lane * 2);
            float m = -INFINITY, ssum = 0.f;
            int cnt = 0;

            for (int base = 0; base < T_LEN; base += 32) {
                unsigned mask = __ballot_sync(FULLMASK, khs[base + lane] == qb);
                while (mask) {
                    int j = __ffs(mask) - 1;
                    mask &= mask - 1;
                    int s = base + j;
                    float2 kv = *reinterpret_cast<const float2*>(Kp + (size_t)s * EMB + lane * 2);
                    float p = q.x * kv.x + q.y * kv.y;
#pragma unroll
                    for (int off = 16; off; off >>= 1)
                        p += __shfl_xor_sync(FULLMASK, p, off);
                    float score = p * 0.125f;     // 1/sqrt(64)
                    float mn = fmaxf(m, score);
                    float corr = __expf(m - score > 0.f ? 0.f : m - mn); // safe; m=-inf -> 0
                    corr = __expf(m - mn);
                    float w = __expf(score - mn);
                    float2 vv = *reinterpret_cast<const float2*>(Vp + (size_t)s * EMB + lane * 2);
                    ssum = ssum * corr + w;
                    o0 = o0 * corr + w * vv.x;
                    o1 = o1 * corr + w * vv.y;
                    m = mn;
                    cnt++;
                }
            }
            if (cnt) {
                float inv = 1.f / ssum;
                o0 *= inv; o1 *= inv;
            } else {
                o0 = 0.f; o1 = 0.f;   // query had no in-bucket key -> invalid -> zero
            }
        }
        *reinterpret_cast<float2*>(Op + (size_t)t * EMB + lane * 2) = make_float2(o0, o1);
    }
}

// ---------------------------------------------------------------------------
// Kernel 4: output projection with fused hash-average (A) and fused
// (nb,nt)->(nt,nb) row transpose (C).
// ---------------------------------------------------------------------------
__global__ __launch_bounds__(256) void gemm_out(const float* __restrict__ W,
                                                const float* __restrict__ bias,
                                                float* __restrict__ out)
{
    __shared__ float As[16][132];
    __shared__ float Bs[16][132];
    const int tid = threadIdx.x;
    const int bn = blockIdx.x;
    const int bm = blockIdx.y;
    const int tx = tid & 15, ty = tid >> 4;

    float acc[8][8];
#pragma unroll
    for (int i = 0; i < 8; i++)
#pragma unroll
        for (int j = 0; j < 8; j++) acc[i][j] = 0.f;

    for (int kk = 0; kk < EMB; kk += 16) {
#pragma unroll
        for (int i = 0; i < 2; i++) {
            int idx = tid * 2 + i;
            int rr = idx >> 2, k4 = idx & 3;
            int r = bm * 128 + rr;
            size_t aoff = (size_t)r * EMB + kk + k4 * 4;
            float4 a0 = *reinterpret_cast<const float4*>(&g_att[0][aoff]);
            float4 a1 = *reinterpret_cast<const float4*>(&g_att[1][aoff]);
            As[k4 * 4 + 0][rr] = 0.5f * (a0.x + a1.x);
            As[k4 * 4 + 1][rr] = 0.5f * (a0.y + a1.y);
            As[k4 * 4 + 2][rr] = 0.5f * (a0.z + a1.z);
            As[k4 * 4 + 3][rr] = 0.5f * (a0.w + a1.w);
            float4 bvec = *reinterpret_cast<const float4*>(W + (size_t)(bn * 128 + rr) * EMB + kk + k4 * 4);
            Bs[k4 * 4 + 0][rr] = bvec.x; Bs[k4 * 4 + 1][rr] = bvec.y;
            Bs[k4 * 4 + 2][rr] = bvec.z; Bs[k4 * 4 + 3][rr] = bvec.w;
        }
        __syncthreads();
#pragma unroll
        for (int k = 0; k < 16; k++) {
            float av[8], bv[8];
#pragma unroll
            for (int i = 0; i < 8; i++) av[i] = As[k][ty * 8 + i];
#pragma unroll
            for (int j = 0; j < 8; j++) bv[j] = Bs[k][tx * 8 + j];
#pragma unroll
            for (int i = 0; i < 8; i++)
#pragma unroll
                for (int j = 0; j < 8; j++) acc[i][j] += av[i] * bv[j];
        }
        __syncthreads();
    }

    float bb[8];
#pragma unroll
    for (int j = 0; j < 8; j++) bb[j] = bias[bn * 128 + tx * 8 + j];
#pragma unroll
    for (int i = 0; i < 8; i++) {
        int r = bm * 128 + ty * 8 + i;           // (nb, nt) flat
        int g = (r & 2047) * B_SZ + (r >> 11);   // -> (nt, nb) flat
        float* op = out + (size_t)g * EMB + bn * 128 + tx * 8;
#pragma unroll
        for (int j4 = 0; j4 < 8; j4 += 4) {
            float4 v;
            v.x = acc[i][j4 + 0] + bb[j4 + 0];
            v.y = acc[i][j4 + 1] + bb[j4 + 1];
            v.z = acc[i][j4 + 2] + bb[j4 + 2];
            v.w = acc[i][j4 + 3] + bb[j4 + 3];
            *reinterpret_cast<float4*>(op + j4) = v;
        }
    }
}

// ---------------------------------------------------------------------------
extern "C" void kernel_launch(void* const* d_in, const int* in_sizes, int n_in,
                              void* d_out, int out_size)
{
    (void)in_sizes; (void)n_in; (void)out_size;
    const float* query = (const float*)d_in[0];
    const float* key   = (const float*)d_in[1];
    const float* value = (const float*)d_in[2];
    const float* Wq = (const float*)d_in[3];
    const float* bq = (const float*)d_in[4];
    const float* Wk = (const float*)d_in[5];
    const float* bk = (const float*)d_in[6];
    const float* Wv = (const float*)d_in[7];
    const float* bv = (const float*)d_in[8];
    const float* Wo = (const float*)d_in[9];
    const float* bo = (const float*)d_in[10];
    const float* lshW = (const float*)d_in[11];
    const float* lshb = (const float*)d_in[12];
    float* out = (float*)d_out;

    dim3 gGrid(EMB / 128, ROWS / 128);   // (4, 32)
    gemm_proj<<<gGrid, 256>>>(query, Wq, bq, 0);
    gemm_proj<<<gGrid, 256>>>(key,   Wk, bk, 1);
    gemm_proj<<<gGrid, 256>>>(value, Wv, bv, 2);
    hash_kernel<<<dim3(ROWS * HEADS / 8, 2), 256>>>(lshW, lshb);
    attn_kernel<<<dim3(T_LEN / 64, B_SZ * HEADS, NHASH), 256>>>();
    gemm_out<<<gGrid, 256>>>(Wo, bo, out);
}

// round 4
// speedup vs baseline: 1.7640x; 1.7640x over previous
#include <cuda_runtime.h>
#include <cstdint>

#define T_LEN 2048
#define B_SZ  2
#define EMB   512
#define ROWS  4096       // B*T
#define HEADS 8
#define HDIM  64
#define NHASH 2
#define FULLMASK 0xffffffffu

// ---------------------------------------------------------------------------
// Scratch (no cudaMalloc allowed -> __device__ globals)
// ---------------------------------------------------------------------------
__device__ float g_Q[ROWS * EMB];
__device__ float g_K[ROWS * EMB];
__device__ float g_V[ROWS * EMB];
__device__ unsigned char g_qh[NHASH * B_SZ * HEADS * T_LEN];
__device__ unsigned char g_kh[NHASH * B_SZ * HEADS * T_LEN];
__device__ float g_att[NHASH][ROWS * EMB];
// bucket structures: combo = ((hash*B + b)*HEADS + h), 32 combos
__device__ int g_qstart[32][65];
__device__ int g_kstart[32][65];
__device__ unsigned short g_qlist[32 * T_LEN];
__device__ unsigned short g_klist[32 * T_LEN];

// ---------------------------------------------------------------------------
// Kernel 1: fused QKV projection.
// C[f][e] = sum_k X[src(f)][k] * W[e][k] + bias[e], src(f) = (f&1)*T + (f>>1)
// 128x128 block tile, BK=16, 256 threads, 8x8 per thread.
// ---------------------------------------------------------------------------
__global__ __launch_bounds__(256) void gemm_proj(const float* __restrict__ X,
                                                 const float* __restrict__ W,
                                                 const float* __restrict__ bias,
                                                 int which)
{
    __shared__ float As[16][132];
    __shared__ float Bs[16][132];
    const int tid = threadIdx.x;
    const int bn = blockIdx.x;   // 0..3   (N=512)
    const int bm = blockIdx.y;   // 0..31  (M=4096)
    const int tx = tid & 15, ty = tid >> 4;

    float acc[8][8];
#pragma unroll
    for (int i = 0; i < 8; i++)
#pragma unroll
        for (int j = 0; j < 8; j++) acc[i][j] = 0.f;

    for (int kk = 0; kk < EMB; kk += 16) {
#pragma unroll
        for (int i = 0; i < 2; i++) {
            int idx = tid * 2 + i;          // 0..511
            int rr  = idx >> 2;             // 0..127
            int k4  = idx & 3;
            int r   = bm * 128 + rr;
            int src = (r & 1) * T_LEN + (r >> 1);
            float4 a = *reinterpret_cast<const float4*>(X + (size_t)src * EMB + kk + k4 * 4);
            As[k4 * 4 + 0][rr] = a.x; As[k4 * 4 + 1][rr] = a.y;
            As[k4 * 4 + 2][rr] = a.z; As[k4 * 4 + 3][rr] = a.w;
            float4 b = *reinterpret_cast<const float4*>(W + (size_t)(bn * 128 + rr) * EMB + kk + k4 * 4);
            Bs[k4 * 4 + 0][rr] = b.x; Bs[k4 * 4 + 1][rr] = b.y;
            Bs[k4 * 4 + 2][rr] = b.z; Bs[k4 * 4 + 3][rr] = b.w;
        }
        __syncthreads();
#pragma unroll
        for (int k = 0; k < 16; k++) {
            float av[8], bv[8];
#pragma unroll
            for (int i = 0; i < 8; i++) av[i] = As[k][ty * 8 + i];
#pragma unroll
            for (int j = 0; j < 8; j++) bv[j] = Bs[k][tx * 8 + j];
#pragma unroll
            for (int i = 0; i < 8; i++)
#pragma unroll
                for (int j = 0; j < 8; j++) acc[i][j] += av[i] * bv[j];
        }
        __syncthreads();
    }

    float* outp = (which == 0) ? g_Q : (which == 1) ? g_K : g_V;
    float bb[8];
#pragma unroll
    for (int j = 0; j < 8; j++) bb[j] = bias[bn * 128 + tx * 8 + j];
#pragma unroll
    for (int i = 0; i < 8; i++) {
        int r = bm * 128 + ty * 8 + i;
        float* op = outp + (size_t)r * EMB + bn * 128 + tx * 8;
#pragma unroll
        for (int j4 = 0; j4 < 8; j4 += 4) {
            float4 v;
            v.x = acc[i][j4 + 0] + bb[j4 + 0];
            v.y = acc[i][j4 + 1] + bb[j4 + 1];
            v.z = acc[i][j4 + 2] + bb[j4 + 2];
            v.w = acc[i][j4 + 3] + bb[j4 + 3];
            *reinterpret_cast<float4*>(op + j4) = v;
        }
    }
}

// ---------------------------------------------------------------------------
// Kernel 2: LSH hashing as a register-tiled GEMM + fused argmax.
// A = g_Q (or g_K) viewed as [32768][64]  (row m = flatrow*8 + head)
// B = lshW viewed as [128][64]            (rows 0..63 hash0, 64..127 hash1)
// bias = lshb flat [128].
// S[m][n] = A[m]·B[n] + lshb[n]; bucket(m,hash) = argmax over n-half.
// Tile 128(M) x 128(N), BK=16, 256 threads, 8x8 per thread.
// grid = (256, 2 tensors)
// ---------------------------------------------------------------------------
__global__ __launch_bounds__(256) void hash_gemm(const float* __restrict__ lshW,
                                                 const float* __restrict__ lshb)
{
    __shared__ float As[16][132];
    __shared__ float Bs[16][132];
    const int tid = threadIdx.x;
    const int bm = blockIdx.x;        // 0..255
    const int tensor = blockIdx.y;    // 0 = Q, 1 = K
    const int tx = tid & 15, ty = tid >> 4;
    const int lane = tid & 31;

    const float* A = tensor ? g_K : g_Q;
    unsigned char* dst = tensor ? g_kh : g_qh;

    float acc[8][8];
#pragma unroll
    for (int i = 0; i < 8; i++)
#pragma unroll
        for (int j = 0; j < 8; j++) acc[i][j] = 0.f;

    for (int kk = 0; kk < 64; kk += 16) {
#pragma unroll
        for (int i = 0; i < 2; i++) {
            int idx = tid * 2 + i;
            int rr = idx >> 2, k4 = idx & 3;
            int m = bm * 128 + rr;
            float4 a = *reinterpret_cast<const float4*>(A + (size_t)m * 64 + kk + k4 * 4);
            As[k4 * 4 + 0][rr] = a.x; As[k4 * 4 + 1][rr] = a.y;
            As[k4 * 4 + 2][rr] = a.z; As[k4 * 4 + 3][rr] = a.w;
            float4 b = *reinterpret_cast<const float4*>(lshW + (size_t)rr * 64 + kk + k4 * 4);
            Bs[k4 * 4 + 0][rr] = b.x; Bs[k4 * 4 + 1][rr] = b.y;
            Bs[k4 * 4 + 2][rr] = b.z; Bs[k4 * 4 + 3][rr] = b.w;
        }
        __syncthreads();
#pragma unroll
        for (int k = 0; k < 16; k++) {
            float av[8], bv[8];
#pragma unroll
            for (int i = 0; i < 8; i++) av[i] = As[k][ty * 8 + i];
#pragma unroll
            for (int j = 0; j < 8; j++) bv[j] = Bs[k][tx * 8 + j];
#pragma unroll
            for (int i = 0; i < 8; i++)
#pragma unroll
                for (int j = 0; j < 8; j++) acc[i][j] += av[i] * bv[j];
        }
        __syncthreads();
    }

    // epilogue: bias + argmax over each 64-dim half (tx 0..7 = hash0, 8..15 = hash1)
    float bb[8];
#pragma unroll
    for (int j = 0; j < 8; j++) bb[j] = lshb[tx * 8 + j];

    const int dbase = (tx & 7) * 8;   // local d within the hash's 64 dims
    const int hashI = tx >> 3;
#pragma unroll
    for (int i = 0; i < 8; i++) {
        float bv = acc[i][0] + bb[0];
        int   bi = dbase;
#pragma unroll
        for (int j = 1; j < 8; j++) {
            float v = acc[i][j] + bb[j];
            if (v > bv) { bv = v; bi = dbase + j; }
        }
        // reduce within the 8-lane group (same ty, same hash half)
#pragma unroll
        for (int off = 1; off < 8; off <<= 1) {
            float ov = __shfl_xor_sync(FULLMASK, bv, off);
            int   oi = __shfl_xor_sync(FULLMASK, bi, off);
            if (ov > bv || (ov == bv && oi < bi)) { bv = ov; bi = oi; }
        }
        if ((lane & 7) == 0) {
            int m  = bm * 128 + ty * 8 + i;
            int r  = m >> 3, h = m & 7;
            int nb = r >> 11, nt = r & 2047;
            dst[((hashI * B_SZ + nb) * HEADS + h) * T_LEN + nt] = (unsigned char)bi;
        }
    }
}

// ---------------------------------------------------------------------------
// Kernel 3: bucketize — counting sort of query/key token ids per combo.
// grid = 32 blocks (one per combo), 256 threads.
// ---------------------------------------------------------------------------
__global__ __launch_bounds__(256) void bucketize_kernel()
{
    __shared__ int cnt[2][64];
    __shared__ int off[2][64];
    const int combo = blockIdx.x;
    const int tid = threadIdx.x;

    for (int i = tid; i < 128; i += 256) cnt[i >> 6][i & 63] = 0;
    __syncthreads();

    const unsigned char* qh = g_qh + combo * T_LEN;
    const unsigned char* kh = g_kh + combo * T_LEN;
    for (int i = tid; i < T_LEN; i += 256) {
        atomicAdd(&cnt[0][qh[i]], 1);
        atomicAdd(&cnt[1][kh[i]], 1);
    }
    __syncthreads();

    if (tid == 0) {
        int s = 0;
        for (int j = 0; j < 64; j++) { g_qstart[combo][j] = s; off[0][j] = s; s += cnt[0][j]; }
        g_qstart[combo][64] = s;
    }
    if (tid == 32) {
        int s = 0;
        for (int j = 0; j < 64; j++) { g_kstart[combo][j] = s; off[1][j] = s; s += cnt[1][j]; }
        g_kstart[combo][64] = s;
    }
    __syncthreads();

    for (int i = tid; i < T_LEN; i += 256) {
        int p = atomicAdd(&off[0][qh[i]], 1);
        g_qlist[combo * T_LEN + p] = (unsigned short)i;
        p = atomicAdd(&off[1][kh[i]], 1);
        g_klist[combo * T_LEN + p] = (unsigned short)i;
    }
}

// ---------------------------------------------------------------------------
// Kernel 4: per-bucket attention.
// grid = (64 buckets, 32 combos), 256 threads (8 warps).
// Q/K rows of the bucket staged into padded smem; warp handles 8 queries,
// key-parallel scoring (lane = key, dot from smem) + online softmax with one
// warp-max per 32-key chunk; V accumulated dim-parallel (lane = dim pair).
// Buckets >= 32 (never attended) and empty-key buckets write zeros.
// ---------------------------------------------------------------------------
#define QT 64
#define KT 64

__global__ __launch_bounds__(256) void attn_bucket_kernel()
{
    __shared__ float qsh[QT][68];
    __shared__ float ksh[KT][68];
    __shared__ int   qid[QT];
    __shared__ int   kid[KT];

    const int bucket = blockIdx.x;   // 0..63
    const int combo  = blockIdx.y;   // 0..31
    const int hash = combo >> 4;
    const int b    = (combo >> 3) & 1;
    const int h    = combo & 7;
    const int tid  = threadIdx.x;
    const int warp = tid >> 5, lane = tid & 31;

    const int qs = g_qstart[combo][bucket];
    const int nq = g_qstart[combo][bucket + 1] - qs;
    if (nq == 0) return;
    const int ks = g_kstart[combo][bucket];
    const int kn = g_kstart[combo][bucket + 1] - ks;

    const unsigned short* qlist = g_qlist + combo * T_LEN;
    const unsigned short* klist = g_klist + combo * T_LEN;

    float* Op = g_att[hash] + (size_t)b * T_LEN * EMB + h * HDIM;

    if (bucket >= 32 || kn == 0) {
        // these queries get zero output for this hash round
        for (int idx = tid; idx < nq * 32; idx += 256) {
            int qi = idx >> 5, l = idx & 31;
            int t = qlist[qs + qi];
            *reinterpret_cast<float2*>(Op + (size_t)t * EMB + l * 2) = make_float2(0.f, 0.f);
        }
        return;
    }

    const float* Qp = g_Q + (size_t)b * T_LEN * EMB + h * HDIM;
    const float* Kp = g_K + (size_t)b * T_LEN * EMB + h * HDIM;
    const float* Vp = g_V + (size_t)b * T_LEN * EMB + h * HDIM;

    const int nqt = (nq + QT - 1) / QT;
    const int nkc = (kn + KT - 1) / KT;

    for (int qt = 0; qt < nqt; qt++) {
        const int cq = min(QT, nq - qt * QT);
        __syncthreads();
        for (int task = tid; task < QT * 16; task += 256) {
            int row = task >> 4, slot = task & 15;
            if (row < cq) {
                int t = qlist[qs + qt * QT + row];
                if (slot == 0) qid[row] = t;
                *reinterpret_cast<float4*>(&qsh[row][slot * 4]) =
                    *reinterpret_cast<const float4*>(Qp + (size_t)t * EMB + slot * 4);
            }
        }
        __syncthreads();

        float m[8], ss[8], o0[8], o1[8];
#pragma unroll
        for (int i = 0; i < 8; i++) { m[i] = -INFINITY; ss[i] = 0.f; o0[i] = 0.f; o1[i] = 0.f; }

        for (int kc = 0; kc < nkc; kc++) {
            const int cnk = min(KT, kn - kc * KT);
            __syncthreads();
            for (int task = tid; task < KT * 16; task += 256) {
                int row = task >> 4, slot = task & 15;
                if (row < cnk) {
                    int t = klist[ks + kc * KT + row];
                    if (slot == 0) kid[row] = t;
                    *reinterpret_cast<float4*>(&ksh[row][slot * 4]) =
                        *reinterpret_cast<const float4*>(Kp + (size_t)t * EMB + slot * 4);
                }
            }
            __syncthreads();

#pragma unroll
            for (int i = 0; i < 8; i++) {
                const int qrow = warp * 8 + i;      // warp-uniform validity
                if (qrow >= cq) continue;
                const int nsubs = (cnk + 31) >> 5;
                for (int sub = 0; sub < nsubs; sub++) {
                    const int nsub = min(32, cnk - sub * 32);
                    const int kr = (lane < nsub) ? (sub * 32 + lane) : 0;
                    float dot = 0.f;
#pragma unroll
                    for (int j = 0; j < 16; j++) {
                        float4 kv = *reinterpret_cast<const float4*>(&ksh[kr][j * 4]);
                        float4 qv = *reinterpret_cast<const float4*>(&qsh[qrow][j * 4]);
                        dot += kv.x * qv.x + kv.y * qv.y + kv.z * qv.z + kv.w * qv.w;
                    }
                    float s = (lane < nsub) ? dot * 0.125f : -INFINITY;
                    float cm = s;
#pragma unroll
                    for (int off = 16; off; off >>= 1)
                        cm = fmaxf(cm, __shfl_xor_sync(FULLMASK, cm, off));
                    const float mn = fmaxf(m[i], cm);
                    const float corr = __expf(m[i] - mn);   // m=-inf -> 0
                    const float w = __expf(s - mn);          // s=-inf -> 0
                    ss[i] = ss[i] * corr + w;                // per-lane partial
                    o0[i] *= corr; o1[i] *= corr;
                    m[i] = mn;
                    for (int j = 0; j < nsub; j++) {
                        float wj = __shfl_sync(FULLMASK, w, j);
                        int kt_ = kid[sub * 32 + j];
                        float2 vv = *reinterpret_cast<const float2*>(Vp + (size_t)kt_ * EMB + lane * 2);
                        o0[i] += wj * vv.x;
                        o1[i] += wj * vv.y;
                    }
                }
            }
        }

#pragma unroll
        for (int i = 0; i < 8; i++) {
            const int qrow = warp * 8 + i;
            if (qrow >= cq) continue;
            float tot = ss[i];
#pragma unroll
            for (int off = 16; off; off >>= 1)
                tot += __shfl_xor_sync(FULLMASK, tot, off);
            const float inv = 1.f / tot;
            int t = qid[qrow];
            *reinterpret_cast<float2*>(Op + (size_t)t * EMB + lane * 2) =
                make_float2(o0[i] * inv, o1[i] * inv);
        }
    }
}

// ---------------------------------------------------------------------------
// Kernel 5: output projection with fused hash-average (A) and fused
// (nb,nt)->(nt,nb) row transpose (C).
// ---------------------------------------------------------------------------
__global__ __launch_bounds__(256) void gemm_out(const float* __restrict__ W,
                                                const float* __restrict__ bias,
                                                float* __restrict__ out)
{
    __shared__ float As[16][132];
    __shared__ float Bs[16][132];
    const int tid = threadIdx.x;
    const int bn = blockIdx.x;
    const int bm = blockIdx.y;
    const int tx = tid & 15, ty = tid >> 4;

    float acc[8][8];
#pragma unroll
    for (int i = 0; i < 8; i++)
#pragma unroll
        for (int j = 0; j < 8; j++) acc[i][j] = 0.f;

    for (int kk = 0; kk < EMB; kk += 16) {
#pragma unroll
        for (int i = 0; i < 2; i++) {
            int idx = tid * 2 + i;
            int rr = idx >> 2, k4 = idx & 3;
            int r = bm * 128 + rr;
            size_t aoff = (size_t)r * EMB + kk + k4 * 4;
            float4 a0 = *reinterpret_cast<const float4*>(&g_att[0][aoff]);
            float4 a1 = *reinterpret_cast<const float4*>(&g_att[1][aoff]);
            As[k4 * 4 + 0][rr] = 0.5f * (a0.x + a1.x);
            As[k4 * 4 + 1][rr] = 0.5f * (a0.y + a1.y);
            As[k4 * 4 + 2][rr] = 0.5f * (a0.z + a1.z);
            As[k4 * 4 + 3][rr] = 0.5f * (a0.w + a1.w);
            float4 bvec = *reinterpret_cast<const float4*>(W + (size_t)(bn * 128 + rr) * EMB + kk + k4 * 4);
            Bs[k4 * 4 + 0][rr] = bvec.x; Bs[k4 * 4 + 1][rr] = bvec.y;
            Bs[k4 * 4 + 2][rr] = bvec.z; Bs[k4 * 4 + 3][rr] = bvec.w;
        }
        __syncthreads();
#pragma unroll
        for (int k = 0; k < 16; k++) {
            float av[8], bv[8];
#pragma unroll
            for (int i = 0; i < 8; i++) av[i] = As[k][ty * 8 + i];
#pragma unroll
            for (int j = 0; j < 8; j++) bv[j] = Bs[k][tx * 8 + j];
#pragma unroll
            for (int i = 0; i < 8; i++)
#pragma unroll
                for (int j = 0; j < 8; j++) acc[i][j] += av[i] * bv[j];
        }
        __syncthreads();
    }

    float bb[8];
#pragma unroll
    for (int j = 0; j < 8; j++) bb[j] = bias[bn * 128 + tx * 8 + j];
#pragma unroll
    for (int i = 0; i < 8; i++) {
        int r = bm * 128 + ty * 8 + i;           // (nb, nt) flat
        int g = (r & 2047) * B_SZ + (r >> 11);   // -> (nt, nb) flat
        float* op = out + (size_t)g * EMB + bn * 128 + tx * 8;
#pragma unroll
        for (int j4 = 0; j4 < 8; j4 += 4) {
            float4 v;
            v.x = acc[i][j4 + 0] + bb[j4 + 0];
            v.y = acc[i][j4 + 1] + bb[j4 + 1];
            v.z = acc[i][j4 + 2] + bb[j4 + 2];
            v.w = acc[i][j4 + 3] + bb[j4 + 3];
            *reinterpret_cast<float4*>(op + j4) = v;
        }
    }
}

// ---------------------------------------------------------------------------
extern "C" void kernel_launch(void* const* d_in, const int* in_sizes, int n_in,
                              void* d_out, int out_size)
{
    (void)in_sizes; (void)n_in; (void)out_size;
    const float* query = (const float*)d_in[0];
    const float* key   = (const float*)d_in[1];
    const float* value = (const float*)d_in[2];
    const float* Wq = (const float*)d_in[3];
    const float* bq = (const float*)d_in[4];
    const float* Wk = (const float*)d_in[5];
    const float* bk = (const float*)d_in[6];
    const float* Wv = (const float*)d_in[7];
    const float* bv = (const float*)d_in[8];
    const float* Wo = (const float*)d_in[9];
    const float* bo = (const float*)d_in[10];
    const float* lshW = (const float*)d_in[11];
    const float* lshb = (const float*)d_in[12];
    float* out = (float*)d_out;

    dim3 gGrid(EMB / 128, ROWS / 128);   // (4, 32)
    gemm_proj<<<gGrid, 256>>>(query, Wq, bq, 0);
    gemm_proj<<<gGrid, 256>>>(key,   Wk, bk, 1);
    gemm_proj<<<gGrid, 256>>>(value, Wv, bv, 2);
    hash_gemm<<<dim3(256, 2), 256>>>(lshW, lshb);
    bucketize_kernel<<<32, 256>>>();
    attn_bucket_kernel<<<dim3(64, 32), 256>>>();
    gemm_out<<<gGrid, 256>>>(Wo, bo, out);
}

// round 5
// speedup vs baseline: 1.8224x; 1.0331x over previous
#include <cuda_runtime.h>
#include <cstdint>

#define T_LEN 2048
#define B_SZ  2
#define EMB   512
#define ROWS  4096       // B*T
#define HEADS 8
#define HDIM  64
#define NHASH 2
#define FULLMASK 0xffffffffu

// ---------------------------------------------------------------------------
// Scratch
// ---------------------------------------------------------------------------
__device__ float g_Q[ROWS * EMB];
__device__ float g_K[ROWS * EMB];
__device__ float g_V[ROWS * EMB];
__device__ unsigned char g_qh[NHASH * B_SZ * HEADS * T_LEN];
__device__ unsigned char g_kh[NHASH * B_SZ * HEADS * T_LEN];
__device__ float g_att[NHASH][ROWS * EMB];
__device__ int g_qstart[32][65];
__device__ int g_kstart[32][65];
__device__ unsigned short g_qlist[32 * T_LEN];
__device__ unsigned short g_klist[32 * T_LEN];

// ---------------------------------------------------------------------------
// Shared 128x128 FFMA tile compute (BK=16, 256 threads, 8x8/thread)
// ---------------------------------------------------------------------------
__device__ __forceinline__ void tile_fma(const float (*A)[132], const float (*B)[132],
                                         float acc[8][8], int tx, int ty)
{
#pragma unroll
    for (int k = 0; k < 16; k++) {
        float av[8], bv[8];
#pragma unroll
        for (int i = 0; i < 8; i++) av[i] = A[k][ty * 8 + i];
#pragma unroll
        for (int j = 0; j < 8; j++) bv[j] = B[k][tx * 8 + j];
#pragma unroll
        for (int i = 0; i < 8; i++)
#pragma unroll
            for (int j = 0; j < 8; j++) acc[i][j] += av[i] * bv[j];
    }
}

// ---------------------------------------------------------------------------
// Kernel 1: fused QKV projection, double-buffered.
// z selects (X, W, bias, out). A-row remap src(f) = (f&1)*T + (f>>1).
// ---------------------------------------------------------------------------
__global__ __launch_bounds__(256, 2) void gemm_qkv(
    const float* __restrict__ Xq, const float* __restrict__ Xk, const float* __restrict__ Xv,
    const float* __restrict__ Wq, const float* __restrict__ Wk, const float* __restrict__ Wv,
    const float* __restrict__ bq, const float* __restrict__ bk, const float* __restrict__ bv)
{
    __shared__ float As[2][16][132];
    __shared__ float Bs[2][16][132];
    const int tid = threadIdx.x;
    const int bn = blockIdx.x;   // 0..3
    const int bm = blockIdx.y;   // 0..31
    const int z  = blockIdx.z;   // 0..2
    const int tx = tid & 15, ty = tid >> 4;

    const float* X = (z == 0) ? Xq : (z == 1) ? Xk : Xv;
    const float* W = (z == 0) ? Wq : (z == 1) ? Wk : Wv;
    const float* bias = (z == 0) ? bq : (z == 1) ? bk : bv;
    float* outp = (z == 0) ? g_Q : (z == 1) ? g_K : g_V;

    // per-thread staging coordinates: row rr, two adjacent float4 along k
    const int rr = tid >> 1;
    const int k4 = (tid & 1) * 2;
    const int r = bm * 128 + rr;
    const int src = (r & 1) * T_LEN + (r >> 1);
    const float* Aptr = X + (size_t)src * EMB + k4 * 4;
    const float* Bptr = W + (size_t)(bn * 128 + rr) * EMB + k4 * 4;

    float acc[8][8];
#pragma unroll
    for (int i = 0; i < 8; i++)
#pragma unroll
        for (int j = 0; j < 8; j++) acc[i][j] = 0.f;

    float4 ra0 = *reinterpret_cast<const float4*>(Aptr);
    float4 ra1 = *reinterpret_cast<const float4*>(Aptr + 4);
    float4 rb0 = *reinterpret_cast<const float4*>(Bptr);
    float4 rb1 = *reinterpret_cast<const float4*>(Bptr + 4);
    {
        float* a = &As[0][k4 * 4][rr];
        a[0 * 132] = ra0.x; a[1 * 132] = ra0.y; a[2 * 132] = ra0.z; a[3 * 132] = ra0.w;
        a[4 * 132] = ra1.x; a[5 * 132] = ra1.y; a[6 * 132] = ra1.z; a[7 * 132] = ra1.w;
        float* b = &Bs[0][k4 * 4][rr];
        b[0 * 132] = rb0.x; b[1 * 132] = rb0.y; b[2 * 132] = rb0.z; b[3 * 132] = rb0.w;
        b[4 * 132] = rb1.x; b[5 * 132] = rb1.y; b[6 * 132] = rb1.z; b[7 * 132] = rb1.w;
    }
    __syncthreads();

    const int NS = EMB / 16;
    for (int s = 0; s < NS; s++) {
        const int cur = s & 1;
        if (s + 1 < NS) {
            const float* ap = Aptr + (s + 1) * 16;
            const float* bp = Bptr + (s + 1) * 16;
            ra0 = *reinterpret_cast<const float4*>(ap);
            ra1 = *reinterpret_cast<const float4*>(ap + 4);
            rb0 = *reinterpret_cast<const float4*>(bp);
            rb1 = *reinterpret_cast<const float4*>(bp + 4);
        }
        tile_fma(As[cur], Bs[cur], acc, tx, ty);
        if (s + 1 < NS) {
            __syncthreads();
            float* a = &As[cur ^ 1][k4 * 4][rr];
            a[0 * 132] = ra0.x; a[1 * 132] = ra0.y; a[2 * 132] = ra0.z; a[3 * 132] = ra0.w;
            a[4 * 132] = ra1.x; a[5 * 132] = ra1.y; a[6 * 132] = ra1.z; a[7 * 132] = ra1.w;
            float* b = &Bs[cur ^ 1][k4 * 4][rr];
            b[0 * 132] = rb0.x; b[1 * 132] = rb0.y; b[2 * 132] = rb0.z; b[3 * 132] = rb0.w;
            b[4 * 132] = rb1.x; b[5 * 132] = rb1.y; b[6 * 132] = rb1.z; b[7 * 132] = rb1.w;
            __syncthreads();
        }
    }

    float bb[8];
#pragma unroll
    for (int j = 0; j < 8; j++) bb[j] = bias[bn * 128 + tx * 8 + j];
#pragma unroll
    for (int i = 0; i < 8; i++) {
        int ro = bm * 128 + ty * 8 + i;
        float* op = outp + (size_t)ro * EMB + bn * 128 + tx * 8;
#pragma unroll
        for (int j4 = 0; j4 < 8; j4 += 4) {
            float4 v;
            v.x = acc[i][j4 + 0] + bb[j4 + 0];
            v.y = acc[i][j4 + 1] + bb[j4 + 1];
            v.z = acc[i][j4 + 2] + bb[j4 + 2];
            v.w = acc[i][j4 + 3] + bb[j4 + 3];
            *reinterpret_cast<float4*>(op + j4) = v;
        }
    }
}

// ---------------------------------------------------------------------------
// Kernel 2: LSH hashing GEMM, 64(M)x128(N) tile, BK=16, fused argmax.
// A = g_Q/g_K as [32768][64]; B = lshW [128][64]; grid (512, 2).
// ---------------------------------------------------------------------------
__global__ __launch_bounds__(256) void hash_gemm(const float* __restrict__ lshW,
                                                 const float* __restrict__ lshb)
{
    __shared__ float As[16][68];
    __shared__ float Bs[16][132];
    const int tid = threadIdx.x;
    const int bm = blockIdx.x;        // 0..511
    const int tensor = blockIdx.y;    // 0 = Q, 1 = K
    const int tx = tid & 15, ty = tid >> 4;
    const int lane = tid & 31;

    const float* A = tensor ? g_K : g_Q;
    unsigned char* dst = tensor ? g_kh : g_qh;

    float acc[4][8];
#pragma unroll
    for (int i = 0; i < 4; i++)
#pragma unroll
        for (int j = 0; j < 8; j++) acc[i][j] = 0.f;

    for (int kk = 0; kk < 64; kk += 16) {
        // A: 64 rows x 16k = 256 float4 slots, one per thread
        {
            int arr = tid >> 2, ak4 = tid & 3;
            float4 a = *reinterpret_cast<const float4*>(A + (size_t)(bm * 64 + arr) * 64 + kk + ak4 * 4);
            As[ak4 * 4 + 0][arr] = a.x; As[ak4 * 4 + 1][arr] = a.y;
            As[ak4 * 4 + 2][arr] = a.z; As[ak4 * 4 + 3][arr] = a.w;
        }
        // B: 128 rows x 16k = 512 slots, two per thread
#pragma unroll
        for (int i = 0; i < 2; i++) {
            int idx = tid * 2 + i;
            int rr = idx >> 2, bk4 = idx & 3;
            float4 b = *reinterpret_cast<const float4*>(lshW + (size_t)rr * 64 + kk + bk4 * 4);
            Bs[bk4 * 4 + 0][rr] = b.x; Bs[bk4 * 4 + 1][rr] = b.y;
            Bs[bk4 * 4 + 2][rr] = b.z; Bs[bk4 * 4 + 3][rr] = b.w;
        }
        __syncthreads();
#pragma unroll
        for (int k = 0; k < 16; k++) {
            float av[4], bv[8];
#pragma unroll
            for (int i = 0; i < 4; i++) av[i] = As[k][ty * 4 + i];
#pragma unroll
            for (int j = 0; j < 8; j++) bv[j] = Bs[k][tx * 8 + j];
#pragma unroll
            for (int i = 0; i < 4; i++)
#pragma unroll
                for (int j = 0; j < 8; j++) acc[i][j] += av[i] * bv[j];
        }
        __syncthreads();
    }

    float bb[8];
#pragma unroll
    for (int j = 0; j < 8; j++) bb[j] = lshb[tx * 8 + j];

    const int dbase = (tx & 7) * 8;
    const int hashI = tx >> 3;
#pragma unroll
    for (int i = 0; i < 4; i++) {
        float bv = acc[i][0] + bb[0];
        int   bi = dbase;
#pragma unroll
        for (int j = 1; j < 8; j++) {
            float v = acc[i][j] + bb[j];
            if (v > bv) { bv = v; bi = dbase + j; }
        }
#pragma unroll
        for (int off = 1; off < 8; off <<= 1) {
            float ov = __shfl_xor_sync(FULLMASK, bv, off);
            int   oi = __shfl_xor_sync(FULLMASK, bi, off);
            if (ov > bv || (ov == bv && oi < bi)) { bv = ov; bi = oi; }
        }
        if ((lane & 7) == 0) {
            int m  = bm * 64 + ty * 4 + i;
            int r  = m >> 3, h = m & 7;
            int nb = r >> 11, nt = r & 2047;
            dst[((hashI * B_SZ + nb) * HEADS + h) * T_LEN + nt] = (unsigned char)bi;
        }
    }
}

// ---------------------------------------------------------------------------
// Kernel 3: bucketize
// ---------------------------------------------------------------------------
__global__ __launch_bounds__(256) void bucketize_kernel()
{
    __shared__ int cnt[2][64];
    __shared__ int off[2][64];
    const int combo = blockIdx.x;
    const int tid = threadIdx.x;

    for (int i = tid; i < 128; i += 256) cnt[i >> 6][i & 63] = 0;
    __syncthreads();

    const unsigned char* qh = g_qh + combo * T_LEN;
    const unsigned char* kh = g_kh + combo * T_LEN;
    for (int i = tid; i < T_LEN; i += 256) {
        atomicAdd(&cnt[0][qh[i]], 1);
        atomicAdd(&cnt[1][kh[i]], 1);
    }
    __syncthreads();

    if (tid == 0) {
        int s = 0;
        for (int j = 0; j < 64; j++) { g_qstart[combo][j] = s; off[0][j] = s; s += cnt[0][j]; }
        g_qstart[combo][64] = s;
    }
    if (tid == 32) {
        int s = 0;
        for (int j = 0; j < 64; j++) { g_kstart[combo][j] = s; off[1][j] = s; s += cnt[1][j]; }
        g_kstart[combo][64] = s;
    }
    __syncthreads();

    for (int i = tid; i < T_LEN; i += 256) {
        int p = atomicAdd(&off[0][qh[i]], 1);
        g_qlist[combo * T_LEN + p] = (unsigned short)i;
        p = atomicAdd(&off[1][kh[i]], 1);
        g_klist[combo * T_LEN + p] = (unsigned short)i;
    }
}

// ---------------------------------------------------------------------------
// Kernel 4: per-bucket attention (unchanged from round 3)
// ---------------------------------------------------------------------------
#define QT 64
#define KT 64

__global__ __launch_bounds__(256) void attn_bucket_kernel()
{
    __shared__ float qsh[QT][68];
    __shared__ float ksh[KT][68];
    __shared__ int   qid[QT];
    __shared__ int   kid[KT];

    const int bucket = blockIdx.x;
    const int combo  = blockIdx.y;
    const int hash = combo >> 4;
    const int b    = (combo >> 3) & 1;
    const int h    = combo & 7;
    const int tid  = threadIdx.x;
    const int warp = tid >> 5, lane = tid & 31;

    const int qs = g_qstart[combo][bucket];
    const int nq = g_qstart[combo][bucket + 1] - qs;
    if (nq == 0) return;
    const int ks = g_kstart[combo][bucket];
    const int kn = g_kstart[combo][bucket + 1] - ks;

    const unsigned short* qlist = g_qlist + combo * T_LEN;
    const unsigned short* klist = g_klist + combo * T_LEN;

    float* Op = g_att[hash] + (size_t)b * T_LEN * EMB + h * HDIM;

    if (bucket >= 32 || kn == 0) {
        for (int idx = tid; idx < nq * 32; idx += 256) {
            int qi = idx >> 5, l = idx & 31;
            int t = qlist[qs + qi];
            *reinterpret_cast<float2*>(Op + (size_t)t * EMB + l * 2) = make_float2(0.f, 0.f);
        }
        return;
    }

    const float* Qp = g_Q + (size_t)b * T_LEN * EMB + h * HDIM;
    const float* Kp = g_K + (size_t)b * T_LEN * EMB + h * HDIM;
    const float* Vp = g_V + (size_t)b * T_LEN * EMB + h * HDIM;

    const int nqt = (nq + QT - 1) / QT;
    const int nkc = (kn + KT - 1) / KT;

    for (int qt = 0; qt < nqt; qt++) {
        const int cq = min(QT, nq - qt * QT);
        __syncthreads();
        for (int task = tid; task < QT * 16; task += 256) {
            int row = task >> 4, slot = task & 15;
            if (row < cq) {
                int t = qlist[qs + qt * QT + row];
                if (slot == 0) qid[row] = t;
                *reinterpret_cast<float4*>(&qsh[row][slot * 4]) =
                    *reinterpret_cast<const float4*>(Qp + (size_t)t * EMB + slot * 4);
            }
        }
        __syncthreads();

        float m[8], ss[8], o0[8], o1[8];
#pragma unroll
        for (int i = 0; i < 8; i++) { m[i] = -INFINITY; ss[i] = 0.f; o0[i] = 0.f; o1[i] = 0.f; }

        for (int kc = 0; kc < nkc; kc++) {
            const int cnk = min(KT, kn - kc * KT);
            __syncthreads();
            for (int task = tid; task < KT * 16; task += 256) {
                int row = task >> 4, slot = task & 15;
                if (row < cnk) {
                    int t = klist[ks + kc * KT + row];
                    if (slot == 0) kid[row] = t;
                    *reinterpret_cast<float4*>(&ksh[row][slot * 4]) =
                        *reinterpret_cast<const float4*>(Kp + (size_t)t * EMB + slot * 4);
                }
            }
            __syncthreads();

#pragma unroll
            for (int i = 0; i < 8; i++) {
                const int qrow = warp * 8 + i;
                if (qrow >= cq) continue;
                const int nsubs = (cnk + 31) >> 5;
                for (int sub = 0; sub < nsubs; sub++) {
                    const int nsub = min(32, cnk - sub * 32);
                    const int kr = (lane < nsub) ? (sub * 32 + lane) : 0;
                    float dot = 0.f;
#pragma unroll
                    for (int j = 0; j < 16; j++) {
                        float4 kv = *reinterpret_cast<const float4*>(&ksh[kr][j * 4]);
                        float4 qv = *reinterpret_cast<const float4*>(&qsh[qrow][j * 4]);
                        dot += kv.x * qv.x + kv.y * qv.y + kv.z * qv.z + kv.w * qv.w;
                    }
                    float s = (lane < nsub) ? dot * 0.125f : -INFINITY;
                    float cm = s;
#pragma unroll
                    for (int off = 16; off; off >>= 1)
                        cm = fmaxf(cm, __shfl_xor_sync(FULLMASK, cm, off));
                    const float mn = fmaxf(m[i], cm);
                    const float corr = __expf(m[i] - mn);
                    const float w = __expf(s - mn);
                    ss[i] = ss[i] * corr + w;
                    o0[i] *= corr; o1[i] *= corr;
                    m[i] = mn;
                    for (int j = 0; j < nsub; j++) {
                        float wj = __shfl_sync(FULLMASK, w, j);
                        int kt_ = kid[sub * 32 + j];
                        float2 vv = *reinterpret_cast<const float2*>(Vp + (size_t)kt_ * EMB + lane * 2);
                        o0[i] += wj * vv.x;
                        o1[i] += wj * vv.y;
                    }
                }
            }
        }

#pragma unroll
        for (int i = 0; i < 8; i++) {
            const int qrow = warp * 8 + i;
            if (qrow >= cq) continue;
            float tot = ss[i];
#pragma unroll
            for (int off = 16; off; off >>= 1)
                tot += __shfl_xor_sync(FULLMASK, tot, off);
            const float inv = 1.f / tot;
            int t = qid[qrow];
            *reinterpret_cast<float2*>(Op + (size_t)t * EMB + lane * 2) =
                make_float2(o0[i] * inv, o1[i] * inv);
        }
    }
}

// ---------------------------------------------------------------------------
// Kernel 5: output projection, double-buffered, fused hash-average +
// (nb,nt)->(nt,nb) transpose on store.
// ---------------------------------------------------------------------------
__global__ __launch_bounds__(256, 2) void gemm_out(const float* __restrict__ W,
                                                   const float* __restrict__ bias,
                                                   float* __restrict__ out)
{
    __shared__ float As[2][16][132];
    __shared__ float Bs[2][16][132];
    const int tid = threadIdx.x;
    const int bn = blockIdx.x;
    const int bm = blockIdx.y;
    const int tx = tid & 15, ty = tid >> 4;

    const int rr = tid >> 1;
    const int k4 = (tid & 1) * 2;
    const int r = bm * 128 + rr;
    const float* A0 = &g_att[0][(size_t)r * EMB + k4 * 4];
    const float* A1 = &g_att[1][(size_t)r * EMB + k4 * 4];
    const float* Bptr = W + (size_t)(bn * 128 + rr) * EMB + k4 * 4;

    float acc[8][8];
#pragma unroll
    for (int i = 0; i < 8; i++)
#pragma unroll
        for (int j = 0; j < 8; j++) acc[i][j] = 0.f;

    float4 ra0, ra1, rb0, rb1;
    {
        float4 x0 = *reinterpret_cast<const float4*>(A0);
        float4 y0 = *reinterpret_cast<const float4*>(A1);
        float4 x1 = *reinterpret_cast<const float4*>(A0 + 4);
        float4 y1 = *reinterpret_cast<const float4*>(A1 + 4);
        ra0 = make_float4(0.5f * (x0.x + y0.x), 0.5f * (x0.y + y0.y), 0.5f * (x0.z + y0.z), 0.5f * (x0.w + y0.w));
        ra1 = make_float4(0.5f * (x1.x + y1.x), 0.5f * (x1.y + y1.y), 0.5f * (x1.z + y1.z), 0.5f * (x1.w + y1.w));
        rb0 = *reinterpret_cast<const float4*>(Bptr);
        rb1 = *reinterpret_cast<const float4*>(Bptr + 4);
        float* a = &As[0][k4 * 4][rr];
        a[0 * 132] = ra0.x; a[1 * 132] = ra0.y; a[2 * 132] = ra0.z; a[3 * 132] = ra0.w;
        a[4 * 132] = ra1.x; a[5 * 132] = ra1.y; a[6 * 132] = ra1.z; a[7 * 132] = ra1.w;
        float* b = &Bs[0][k4 * 4][rr];
        b[0 * 132] = rb0.x; b[1 * 132] = rb0.y; b[2 * 132] = rb0.z; b[3 * 132] = rb0.w;
        b[4 * 132] = rb1.x; b[5 * 132] = rb1.y; b[6 * 132] = rb1.z; b[7 * 132] = rb1.w;
    }
    __syncthreads();

    const int NS = EMB / 16;
    for (int s = 0; s < NS; s++) {
        const int cur = s & 1;
        if (s + 1 < NS) {
            const int o = (s + 1) * 16;
            float4 x0 = *reinterpret_cast<const float4*>(A0 + o);
            float4 y0 = *reinterpret_cast<const float4*>(A1 + o);
            float4 x1 = *reinterpret_cast<const float4*>(A0 + o + 4);
            float4 y1 = *reinterpret_cast<const float4*>(A1 + o + 4);
            ra0 = make_float4(0.5f * (x0.x + y0.x), 0.5f * (x0.y + y0.y), 0.5f * (x0.z + y0.z), 0.5f * (x0.w + y0.w));
            ra1 = make_float4(0.5f * (x1.x + y1.x), 0.5f * (x1.y + y1.y), 0.5f * (x1.z + y1.z), 0.5f * (x1.w + y1.w));
            rb0 = *reinterpret_cast<const float4*>(Bptr + o);
            rb1 = *reinterpret_cast<const float4*>(Bptr + o + 4);
        }
        tile_fma(As[cur], Bs[cur], acc, tx, ty);
        if (s + 1 < NS) {
            __syncthreads();
            float* a = &As[cur ^ 1][k4 * 4][rr];
            a[0 * 132] = ra0.x; a[1 * 132] = ra0.y; a[2 * 132] = ra0.z; a[3 * 132] = ra0.w;
            a[4 * 132] = ra1.x; a[5 * 132] = ra1.y; a[6 * 132] = ra1.z; a[7 * 132] = ra1.w;
            float* b = &Bs[cur ^ 1][k4 * 4][rr];
            b[0 * 132] = rb0.x; b[1 * 132] = rb0.y; b[2 * 132] = rb0.z; b[3 * 132] = rb0.w;
            b[4 * 132] = rb1.x; b[5 * 132] = rb1.y; b[6 * 132] = rb1.z; b[7 * 132] = rb1.w;
            __syncthreads();
        }
    }

    float bb[8];
#pragma unroll
    for (int j = 0; j < 8; j++) bb[j] = bias[bn * 128 + tx * 8 + j];
#pragma unroll
    for (int i = 0; i < 8; i++) {
        int ro = bm * 128 + ty * 8 + i;           // (nb, nt) flat
        int g = (ro & 2047) * B_SZ + (ro >> 11);  // -> (nt, nb) flat
        float* op = out + (size_t)g * EMB + bn * 128 + tx * 8;
#pragma unroll
        for (int j4 = 0; j4 < 8; j4 += 4) {
            float4 v;
            v.x = acc[i][j4 + 0] + bb[j4 + 0];
            v.y = acc[i][j4 + 1] + bb[j4 + 1];
            v.z = acc[i][j4 + 2] + bb[j4 + 2];
            v.w = acc[i][j4 + 3] + bb[j4 + 3];
            *reinterpret_cast<float4*>(op + j4) = v;
        }
    }
}

// ---------------------------------------------------------------------------
extern "C" void kernel_launch(void* const* d_in, const int* in_sizes, int n_in,
                              void* d_out, int out_size)
{
    (void)in_sizes; (void)n_in; (void)out_size;
    const float* query = (const float*)d_in[0];
    const float* key   = (const float*)d_in[1];
    const float* value = (const float*)d_in[2];
    const float* Wq = (const float*)d_in[3];
    const float* bq = (const float*)d_in[4];
    const float* Wk = (const float*)d_in[5];
    const float* bk = (const float*)d_in[6];
    const float* Wv = (const float*)d_in[7];
    const float* bv = (const float*)d_in[8];
    const float* Wo = (const float*)d_in[9];
    const float* bo = (const float*)d_in[10];
    const float* lshW = (const float*)d_in[11];
    const float* lshb = (const float*)d_in[12];
    float* out = (float*)d_out;

    gemm_qkv<<<dim3(EMB / 128, ROWS / 128, 3), 256>>>(query, key, value,
                                                      Wq, Wk, Wv, bq, bk, bv);
    hash_gemm<<<dim3(512, 2), 256>>>(lshW, lshb);
    bucketize_kernel<<<32, 256>>>();
    attn_bucket_kernel<<<dim3(64, 32), 256>>>();
    gemm_out<<<dim3(EMB / 128, ROWS / 128), 256>>>(Wo, bo, out);
}

// round 6
// speedup vs baseline: 2.4065x; 1.3206x over previous
#include <cuda_runtime.h>
#include <cstdint>

#define T_LEN 2048
#define B_SZ  2
#define EMB   512
#define ROWS  4096       // B*T
#define HEADS 8
#define HDIM  64
#define NHASH 2
#define FULLMASK 0xffffffffu

// ---------------------------------------------------------------------------
// Scratch
// ---------------------------------------------------------------------------
__device__ float g_Q[ROWS * EMB];
__device__ float g_K[ROWS * EMB];
__device__ float g_V[ROWS * EMB];
__device__ unsigned char g_qh[NHASH * B_SZ * HEADS * T_LEN];
__device__ unsigned char g_kh[NHASH * B_SZ * HEADS * T_LEN];
__device__ float g_att[NHASH][ROWS * EMB];
__device__ int g_qstart[32][65];
__device__ int g_kstart[32][65];
__device__ unsigned short g_qlist[32 * T_LEN];
__device__ unsigned short g_klist[32 * T_LEN];

// ---------------------------------------------------------------------------
// Shared 128x128 FFMA tile compute (BK=16, 256 threads, 8x8/thread)
// ---------------------------------------------------------------------------
__device__ __forceinline__ void tile_fma(const float (*A)[132], const float (*B)[132],
                                         float acc[8][8], int tx, int ty)
{
#pragma unroll
    for (int k = 0; k < 16; k++) {
        float av[8], bv[8];
#pragma unroll
        for (int i = 0; i < 8; i++) av[i] = A[k][ty * 8 + i];
#pragma unroll
        for (int j = 0; j < 8; j++) bv[j] = B[k][tx * 8 + j];
#pragma unroll
        for (int i = 0; i < 8; i++)
#pragma unroll
            for (int j = 0; j < 8; j++) acc[i][j] += av[i] * bv[j];
    }
}

// ---------------------------------------------------------------------------
// Kernel 1: fused QKV projection, double-buffered.
// ---------------------------------------------------------------------------
__global__ __launch_bounds__(256, 2) void gemm_qkv(
    const float* __restrict__ Xq, const float* __restrict__ Xk, const float* __restrict__ Xv,
    const float* __restrict__ Wq, const float* __restrict__ Wk, const float* __restrict__ Wv,
    const float* __restrict__ bq, const float* __restrict__ bk, const float* __restrict__ bv)
{
    __shared__ float As[2][16][132];
    __shared__ float Bs[2][16][132];
    const int tid = threadIdx.x;
    const int bn = blockIdx.x;
    const int bm = blockIdx.y;
    const int z  = blockIdx.z;
    const int tx = tid & 15, ty = tid >> 4;

    const float* X = (z == 0) ? Xq : (z == 1) ? Xk : Xv;
    const float* W = (z == 0) ? Wq : (z == 1) ? Wk : Wv;
    const float* bias = (z == 0) ? bq : (z == 1) ? bk : bv;
    float* outp = (z == 0) ? g_Q : (z == 1) ? g_K : g_V;

    const int rr = tid >> 1;
    const int k4 = (tid & 1) * 2;
    const int r = bm * 128 + rr;
    const int src = (r & 1) * T_LEN + (r >> 1);
    const float* Aptr = X + (size_t)src * EMB + k4 * 4;
    const float* Bptr = W + (size_t)(bn * 128 + rr) * EMB + k4 * 4;

    float acc[8][8];
#pragma unroll
    for (int i = 0; i < 8; i++)
#pragma unroll
        for (int j = 0; j < 8; j++) acc[i][j] = 0.f;

    float4 ra0 = *reinterpret_cast<const float4*>(Aptr);
    float4 ra1 = *reinterpret_cast<const float4*>(Aptr + 4);
    float4 rb0 = *reinterpret_cast<const float4*>(Bptr);
    float4 rb1 = *reinterpret_cast<const float4*>(Bptr + 4);
    {
        float* a = &As[0][k4 * 4][rr];
        a[0 * 132] = ra0.x; a[1 * 132] = ra0.y; a[2 * 132] = ra0.z; a[3 * 132] = ra0.w;
        a[4 * 132] = ra1.x; a[5 * 132] = ra1.y; a[6 * 132] = ra1.z; a[7 * 132] = ra1.w;
        float* b = &Bs[0][k4 * 4][rr];
        b[0 * 132] = rb0.x; b[1 * 132] = rb0.y; b[2 * 132] = rb0.z; b[3 * 132] = rb0.w;
        b[4 * 132] = rb1.x; b[5 * 132] = rb1.y; b[6 * 132] = rb1.z; b[7 * 132] = rb1.w;
    }
    __syncthreads();

    const int NS = EMB / 16;
    for (int s = 0; s < NS; s++) {
        const int cur = s & 1;
        if (s + 1 < NS) {
            const float* ap = Aptr + (s + 1) * 16;
            const float* bp = Bptr + (s + 1) * 16;
            ra0 = *reinterpret_cast<const float4*>(ap);
            ra1 = *reinterpret_cast<const float4*>(ap + 4);
            rb0 = *reinterpret_cast<const float4*>(bp);
            rb1 = *reinterpret_cast<const float4*>(bp + 4);
        }
        tile_fma(As[cur], Bs[cur], acc, tx, ty);
        if (s + 1 < NS) {
            __syncthreads();
            float* a = &As[cur ^ 1][k4 * 4][rr];
            a[0 * 132] = ra0.x; a[1 * 132] = ra0.y; a[2 * 132] = ra0.z; a[3 * 132] = ra0.w;
            a[4 * 132] = ra1.x; a[5 * 132] = ra1.y; a[6 * 132] = ra1.z; a[7 * 132] = ra1.w;
            float* b = &Bs[cur ^ 1][k4 * 4][rr];
            b[0 * 132] = rb0.x; b[1 * 132] = rb0.y; b[2 * 132] = rb0.z; b[3 * 132] = rb0.w;
            b[4 * 132] = rb1.x; b[5 * 132] = rb1.y; b[6 * 132] = rb1.z; b[7 * 132] = rb1.w;
            __syncthreads();
        }
    }

    float bb[8];
#pragma unroll
    for (int j = 0; j < 8; j++) bb[j] = bias[bn * 128 + tx * 8 + j];
#pragma unroll
    for (int i = 0; i < 8; i++) {
        int ro = bm * 128 + ty * 8 + i;
        float* op = outp + (size_t)ro * EMB + bn * 128 + tx * 8;
#pragma unroll
        for (int j4 = 0; j4 < 8; j4 += 4) {
            float4 v;
            v.x = acc[i][j4 + 0] + bb[j4 + 0];
            v.y = acc[i][j4 + 1] + bb[j4 + 1];
            v.z = acc[i][j4 + 2] + bb[j4 + 2];
            v.w = acc[i][j4 + 3] + bb[j4 + 3];
            *reinterpret_cast<float4*>(op + j4) = v;
        }
    }
}

// ---------------------------------------------------------------------------
// Kernel 2: LSH hashing GEMM, 64(M)x128(N) tile + fused argmax.
// ---------------------------------------------------------------------------
__global__ __launch_bounds__(256) void hash_gemm(const float* __restrict__ lshW,
                                                 const float* __restrict__ lshb)
{
    __shared__ float As[16][68];
    __shared__ float Bs[16][132];
    const int tid = threadIdx.x;
    const int bm = blockIdx.x;
    const int tensor = blockIdx.y;
    const int tx = tid & 15, ty = tid >> 4;
    const int lane = tid & 31;

    const float* A = tensor ? g_K : g_Q;
    unsigned char* dst = tensor ? g_kh : g_qh;

    float acc[4][8];
#pragma unroll
    for (int i = 0; i < 4; i++)
#pragma unroll
        for (int j = 0; j < 8; j++) acc[i][j] = 0.f;

    for (int kk = 0; kk < 64; kk += 16) {
        {
            int arr = tid >> 2, ak4 = tid & 3;
            float4 a = *reinterpret_cast<const float4*>(A + (size_t)(bm * 64 + arr) * 64 + kk + ak4 * 4);
            As[ak4 * 4 + 0][arr] = a.x; As[ak4 * 4 + 1][arr] = a.y;
            As[ak4 * 4 + 2][arr] = a.z; As[ak4 * 4 + 3][arr] = a.w;
        }
#pragma unroll
        for (int i = 0; i < 2; i++) {
            int idx = tid * 2 + i;
            int rr = idx >> 2, bk4 = idx & 3;
            float4 b = *reinterpret_cast<const float4*>(lshW + (size_t)rr * 64 + kk + bk4 * 4);
            Bs[bk4 * 4 + 0][rr] = b.x; Bs[bk4 * 4 + 1][rr] = b.y;
            Bs[bk4 * 4 + 2][rr] = b.z; Bs[bk4 * 4 + 3][rr] = b.w;
        }
        __syncthreads();
#pragma unroll
        for (int k = 0; k < 16; k++) {
            float av[4], bv[8];
#pragma unroll
            for (int i = 0; i < 4; i++) av[i] = As[k][ty * 4 + i];
#pragma unroll
            for (int j = 0; j < 8; j++) bv[j] = Bs[k][tx * 8 + j];
#pragma unroll
            for (int i = 0; i < 4; i++)
#pragma unroll
                for (int j = 0; j < 8; j++) acc[i][j] += av[i] * bv[j];
        }
        __syncthreads();
    }

    float bb[8];
#pragma unroll
    for (int j = 0; j < 8; j++) bb[j] = lshb[tx * 8 + j];

    const int dbase = (tx & 7) * 8;
    const int hashI = tx >> 3;
#pragma unroll
    for (int i = 0; i < 4; i++) {
        float bv = acc[i][0] + bb[0];
        int   bi = dbase;
#pragma unroll
        for (int j = 1; j < 8; j++) {
            float v = acc[i][j] + bb[j];
            if (v > bv) { bv = v; bi = dbase + j; }
        }
#pragma unroll
        for (int off = 1; off < 8; off <<= 1) {
            float ov = __shfl_xor_sync(FULLMASK, bv, off);
            int   oi = __shfl_xor_sync(FULLMASK, bi, off);
            if (ov > bv || (ov == bv && oi < bi)) { bv = ov; bi = oi; }
        }
        if ((lane & 7) == 0) {
            int m  = bm * 64 + ty * 4 + i;
            int r  = m >> 3, h = m & 7;
            int nb = r >> 11, nt = r & 2047;
            dst[((hashI * B_SZ + nb) * HEADS + h) * T_LEN + nt] = (unsigned char)bi;
        }
    }
}

// ---------------------------------------------------------------------------
// Kernel 3: bucketize
// ---------------------------------------------------------------------------
__global__ __launch_bounds__(256) void bucketize_kernel()
{
    __shared__ int cnt[2][64];
    __shared__ int off[2][64];
    const int combo = blockIdx.x;
    const int tid = threadIdx.x;

    for (int i = tid; i < 128; i += 256) cnt[i >> 6][i & 63] = 0;
    __syncthreads();

    const unsigned char* qh = g_qh + combo * T_LEN;
    const unsigned char* kh = g_kh + combo * T_LEN;
    for (int i = tid; i < T_LEN; i += 256) {
        atomicAdd(&cnt[0][qh[i]], 1);
        atomicAdd(&cnt[1][kh[i]], 1);
    }
    __syncthreads();

    if (tid == 0) {
        int s = 0;
        for (int j = 0; j < 64; j++) { g_qstart[combo][j] = s; off[0][j] = s; s += cnt[0][j]; }
        g_qstart[combo][64] = s;
    }
    if (tid == 32) {
        int s = 0;
        for (int j = 0; j < 64; j++) { g_kstart[combo][j] = s; off[1][j] = s; s += cnt[1][j]; }
        g_kstart[combo][64] = s;
    }
    __syncthreads();

    for (int i = tid; i < T_LEN; i += 256) {
        int p = atomicAdd(&off[0][qh[i]], 1);
        g_qlist[combo * T_LEN + p] = (unsigned short)i;
        p = atomicAdd(&off[1][kh[i]], 1);
        g_klist[combo * T_LEN + p] = (unsigned short)i;
    }
}

// ---------------------------------------------------------------------------
// Kernel 4: per-bucket dense tiled attention (flash-style).
// grid = (64 buckets, 32 combos), 256 threads.
// Tiles: Q 64x64, K 64x64, V 64x64, P 64x64 in dynamic smem (stride 65).
// Thread (tx,ty) owns 4 q-rows (ty*4+i) and 4 cols (tx*4+j / dims tx*4+d).
// ---------------------------------------------------------------------------
#define AST 65
#define ATT_SMEM (4 * 64 * AST * 4 + 64 * 4)

__global__ __launch_bounds__(256) void attn_bucket_kernel()
{
    extern __shared__ float sm[];
    float* qsh = sm;                    // [64][AST]
    float* ksh = sm + 64 * AST;
    float* vsh = sm + 2 * 64 * AST;
    float* psh = sm + 3 * 64 * AST;
    int*   qid = (int*)(sm + 4 * 64 * AST);

    const int bucket = blockIdx.x;
    const int combo  = blockIdx.y;
    const int hash = combo >> 4;
    const int b    = (combo >> 3) & 1;
    const int h    = combo & 7;
    const int tid  = threadIdx.x;
    const int tx = tid & 15, ty = tid >> 4;

    const int qs = g_qstart[combo][bucket];
    const int nq = g_qstart[combo][bucket + 1] - qs;
    if (nq == 0) return;
    const int ks = g_kstart[combo][bucket];
    const int kn = g_kstart[combo][bucket + 1] - ks;

    const unsigned short* qlist = g_qlist + combo * T_LEN;
    const unsigned short* klist = g_klist + combo * T_LEN;

    float* Op = g_att[hash] + (size_t)b * T_LEN * EMB + h * HDIM;

    if (bucket >= 32 || kn == 0) {
        for (int idx = tid; idx < nq * 16; idx += 256) {
            int qi = idx >> 4, sl = idx & 15;
            int t = qlist[qs + qi];
            *reinterpret_cast<float4*>(Op + (size_t)t * EMB + sl * 4) =
                make_float4(0.f, 0.f, 0.f, 0.f);
        }
        return;
    }

    const float* Qp = g_Q + (size_t)b * T_LEN * EMB + h * HDIM;
    const float* Kp = g_K + (size_t)b * T_LEN * EMB + h * HDIM;
    const float* Vp = g_V + (size_t)b * T_LEN * EMB + h * HDIM;

    for (int q0 = 0; q0 < nq; q0 += 64) {
        const int cq = min(64, nq - q0);
        __syncthreads();
        // load Q tile
        for (int task = tid; task < 64 * 16; task += 256) {
            int row = task >> 4, slot = task & 15;
            if (row < cq) {
                int t = qlist[qs + q0 + row];
                if (slot == 0) qid[row] = t;
                float4 v4 = *reinterpret_cast<const float4*>(Qp + (size_t)t * EMB + slot * 4);
                float* d = &qsh[row * AST + slot * 4];
                d[0] = v4.x; d[1] = v4.y; d[2] = v4.z; d[3] = v4.w;
            }
        }
        __syncthreads();

        float m[4], l[4], o[4][4];
#pragma unroll
        for (int i = 0; i < 4; i++) {
            m[i] = -INFINITY; l[i] = 0.f;
#pragma unroll
            for (int d = 0; d < 4; d++) o[i][d] = 0.f;
        }

        for (int k0 = 0; k0 < kn; k0 += 64) {
            const int cnk = min(64, kn - k0);
            __syncthreads();
            // load K, V tiles (zero-pad V rows >= cnk)
            for (int task = tid; task < 64 * 16; task += 256) {
                int row = task >> 4, slot = task & 15;
                float* dk = &ksh[row * AST + slot * 4];
                float* dv = &vsh[row * AST + slot * 4];
                if (row < cnk) {
                    int t = klist[ks + k0 + row];
                    float4 k4 = *reinterpret_cast<const float4*>(Kp + (size_t)t * EMB + slot * 4);
                    dk[0] = k4.x; dk[1] = k4.y; dk[2] = k4.z; dk[3] = k4.w;
                    float4 v4 = *reinterpret_cast<const float4*>(Vp + (size_t)t * EMB + slot * 4);
                    dv[0] = v4.x; dv[1] = v4.y; dv[2] = v4.z; dv[3] = v4.w;
                } else {
                    dv[0] = 0.f; dv[1] = 0.f; dv[2] = 0.f; dv[3] = 0.f;
                }
            }
            __syncthreads();

            // S = Q @ K^T (4x4 per thread)
            float s4[4][4];
#pragma unroll
            for (int i = 0; i < 4; i++)
#pragma unroll
                for (int j = 0; j < 4; j++) s4[i][j] = 0.f;
#pragma unroll
            for (int k = 0; k < 64; k++) {
                float av[4], bv[4];
#pragma unroll
                for (int i = 0; i < 4; i++) av[i] = qsh[(ty * 4 + i) * AST + k];
#pragma unroll
                for (int j = 0; j < 4; j++) bv[j] = ksh[(tx * 4 + j) * AST + k];
#pragma unroll
                for (int i = 0; i < 4; i++)
#pragma unroll
                    for (int j = 0; j < 4; j++) s4[i][j] += av[i] * bv[j];
            }
            // scale + mask invalid cols
#pragma unroll
            for (int i = 0; i < 4; i++)
#pragma unroll
                for (int j = 0; j < 4; j++)
                    s4[i][j] = (tx * 4 + j < cnk) ? s4[i][j] * 0.125f : -INFINITY;

            // row max across the 16-lane row group
            float cm[4];
#pragma unroll
            for (int i = 0; i < 4; i++) {
                cm[i] = fmaxf(fmaxf(s4[i][0], s4[i][1]), fmaxf(s4[i][2], s4[i][3]));
#pragma unroll
                for (int off = 1; off < 16; off <<= 1)
                    cm[i] = fmaxf(cm[i], __shfl_xor_sync(FULLMASK, cm[i], off));
            }
            // online softmax update
            float corr[4], ps[4];
#pragma unroll
            for (int i = 0; i < 4; i++) {
                float mn = fmaxf(m[i], cm[i]);
                corr[i] = __expf(m[i] - mn);
                m[i] = mn;
                ps[i] = 0.f;
#pragma unroll
                for (int j = 0; j < 4; j++) {
                    float w = __expf(s4[i][j] - mn);
                    s4[i][j] = w;
                    ps[i] += w;
                }
#pragma unroll
                for (int off = 1; off < 16; off <<= 1)
                    ps[i] += __shfl_xor_sync(FULLMASK, ps[i], off);
                l[i] = l[i] * corr[i] + ps[i];
#pragma unroll
                for (int d = 0; d < 4; d++) o[i][d] *= corr[i];
            }
            // stage P
#pragma unroll
            for (int i = 0; i < 4; i++)
#pragma unroll
                for (int j = 0; j < 4; j++)
                    psh[(ty * 4 + i) * AST + tx * 4 + j] = s4[i][j];
            __syncthreads();
            // O += P @ V (4x4 per thread; padded P cols = 0, padded V rows = 0)
#pragma unroll 8
            for (int j = 0; j < 64; j++) {
                float pv[4], vv[4];
#pragma unroll
                for (int i = 0; i < 4; i++) pv[i] = psh[(ty * 4 + i) * AST + j];
#pragma unroll
                for (int d = 0; d < 4; d++) vv[d] = vsh[j * AST + tx * 4 + d];
#pragma unroll
                for (int i = 0; i < 4; i++)
#pragma unroll
                    for (int d = 0; d < 4; d++) o[i][d] += pv[i] * vv[d];
            }
        }

        // store rows
#pragma unroll
        for (int i = 0; i < 4; i++) {
            int row = ty * 4 + i;
            if (row < cq) {
                float inv = 1.f / l[i];
                int t = qid[row];
                float4 v;
                v.x = o[i][0] * inv; v.y = o[i][1] * inv;
                v.z = o[i][2] * inv; v.w = o[i][3] * inv;
                *reinterpret_cast<float4*>(Op + (size_t)t * EMB + tx * 4) = v;
            }
        }
    }
}

// ---------------------------------------------------------------------------
// Kernel 5: output projection, double-buffered, fused hash-average +
// (nb,nt)->(nt,nb) transpose on store.
// ---------------------------------------------------------------------------
__global__ __launch_bounds__(256, 2) void gemm_out(const float* __restrict__ W,
                                                   const float* __restrict__ bias,
                                                   float* __restrict__ out)
{
    __shared__ float As[2][16][132];
    __shared__ float Bs[2][16][132];
    const int tid = threadIdx.x;
    const int bn = blockIdx.x;
    const int bm = blockIdx.y;
    const int tx = tid & 15, ty = tid >> 4;

    const int rr = tid >> 1;
    const int k4 = (tid & 1) * 2;
    const int r = bm * 128 + rr;
    const float* A0 = &g_att[0][(size_t)r * EMB + k4 * 4];
    const float* A1 = &g_att[1][(size_t)r * EMB + k4 * 4];
    const float* Bptr = W + (size_t)(bn * 128 + rr) * EMB + k4 * 4;

    float acc[8][8];
#pragma unroll
    for (int i = 0; i < 8; i++)
#pragma unroll
        for (int j = 0; j < 8; j++) acc[i][j] = 0.f;

    float4 ra0, ra1, rb0, rb1;
    {
        float4 x0 = *reinterpret_cast<const float4*>(A0);
        float4 y0 = *reinterpret_cast<const float4*>(A1);
        float4 x1 = *reinterpret_cast<const float4*>(A0 + 4);
        float4 y1 = *reinterpret_cast<const float4*>(A1 + 4);
        ra0 = make_float4(0.5f * (x0.x + y0.x), 0.5f * (x0.y + y0.y), 0.5f * (x0.z + y0.z), 0.5f * (x0.w + y0.w));
        ra1 = make_float4(0.5f * (x1.x + y1.x), 0.5f * (x1.y + y1.y), 0.5f * (x1.z + y1.z), 0.5f * (x1.w + y1.w));
        rb0 = *reinterpret_cast<const float4*>(Bptr);
        rb1 = *reinterpret_cast<const float4*>(Bptr + 4);
        float* a = &As[0][k4 * 4][rr];
        a[0 * 132] = ra0.x; a[1 * 132] = ra0.y; a[2 * 132] = ra0.z; a[3 * 132] = ra0.w;
        a[4 * 132] = ra1.x; a[5 * 132] = ra1.y; a[6 * 132] = ra1.z; a[7 * 132] = ra1.w;
        float* b = &Bs[0][k4 * 4][rr];
        b[0 * 132] = rb0.x; b[1 * 132] = rb0.y; b[2 * 132] = rb0.z; b[3 * 132] = rb0.w;
        b[4 * 132] = rb1.x; b[5 * 132] = rb1.y; b[6 * 132] = rb1.z; b[7 * 132] = rb1.w;
    }
    __syncthreads();

    const int NS = EMB / 16;
    for (int s = 0; s < NS; s++) {
        const int cur = s & 1;
        if (s + 1 < NS) {
            const int o = (s + 1) * 16;
            float4 x0 = *reinterpret_cast<const float4*>(A0 + o);
            float4 y0 = *reinterpret_cast<const float4*>(A1 + o);
            float4 x1 = *reinterpret_cast<const float4*>(A0 + o + 4);
            float4 y1 = *reinterpret_cast<const float4*>(A1 + o + 4);
            ra0 = make_float4(0.5f * (x0.x + y0.x), 0.5f * (x0.y + y0.y), 0.5f * (x0.z + y0.z), 0.5f * (x0.w + y0.w));
            ra1 = make_float4(0.5f * (x1.x + y1.x), 0.5f * (x1.y + y1.y), 0.5f * (x1.z + y1.z), 0.5f * (x1.w + y1.w));
            rb0 = *reinterpret_cast<const float4*>(Bptr + o);
            rb1 = *reinterpret_cast<const float4*>(Bptr + o + 4);
        }
        tile_fma(As[cur], Bs[cur], acc, tx, ty);
        if (s + 1 < NS) {
            __syncthreads();
            float* a = &As[cur ^ 1][k4 * 4][rr];
            a[0 * 132] = ra0.x; a[1 * 132] = ra0.y; a[2 * 132] = ra0.z; a[3 * 132] = ra0.w;
            a[4 * 132] = ra1.x; a[5 * 132] = ra1.y; a[6 * 132] = ra1.z; a[7 * 132] = ra1.w;
            float* b = &Bs[cur ^ 1][k4 * 4][rr];
            b[0 * 132] = rb0.x; b[1 * 132] = rb0.y; b[2 * 132] = rb0.z; b[3 * 132] = rb0.w;
            b[4 * 132] = rb1.x; b[5 * 132] = rb1.y; b[6 * 132] = rb1.z; b[7 * 132] = rb1.w;
            __syncthreads();
        }
    }

    float bb[8];
#pragma unroll
    for (int j = 0; j < 8; j++) bb[j] = bias[bn * 128 + tx * 8 + j];
#pragma unroll
    for (int i = 0; i < 8; i++) {
        int ro = bm * 128 + ty * 8 + i;           // (nb, nt) flat
        int g = (ro & 2047) * B_SZ + (ro >> 11);  // -> (nt, nb) flat
        float* op = out + (size_t)g * EMB + bn * 128 + tx * 8;
#pragma unroll
        for (int j4 = 0; j4 < 8; j4 += 4) {
            float4 v;
            v.x = acc[i][j4 + 0] + bb[j4 + 0];
            v.y = acc[i][j4 + 1] + bb[j4 + 1];
            v.z = acc[i][j4 + 2] + bb[j4 + 2];
            v.w = acc[i][j4 + 3] + bb[j4 + 3];
            *reinterpret_cast<float4*>(op + j4) = v;
        }
    }
}

// ---------------------------------------------------------------------------
extern "C" void kernel_launch(void* const* d_in, const int* in_sizes, int n_in,
                              void* d_out, int out_size)
{
    (void)in_sizes; (void)n_in; (void)out_size;
    const float* query = (const float*)d_in[0];
    const float* key   = (const float*)d_in[1];
    const float* value = (const float*)d_in[2];
    const float* Wq = (const float*)d_in[3];
    const float* bq = (const float*)d_in[4];
    const float* Wk = (const float*)d_in[5];
    const float* bk = (const float*)d_in[6];
    const float* Wv = (const float*)d_in[7];
    const float* bv = (const float*)d_in[8];
    const float* Wo = (const float*)d_in[9];
    const float* bo = (const float*)d_in[10];
    const float* lshW = (const float*)d_in[11];
    const float* lshb = (const float*)d_in[12];
    float* out = (float*)d_out;

    cudaFuncSetAttribute(attn_bucket_kernel,
                         cudaFuncAttributeMaxDynamicSharedMemorySize, ATT_SMEM);

    gemm_qkv<<<dim3(EMB / 128, ROWS / 128, 3), 256>>>(query, key, value,
                                                      Wq, Wk, Wv, bq, bk, bv);
    hash_gemm<<<dim3(512, 2), 256>>>(lshW, lshb);
    bucketize_kernel<<<32, 256>>>();
    attn_bucket_kernel<<<dim3(64, 32), 256, ATT_SMEM>>>();
    gemm_out<<<dim3(EMB / 128, ROWS / 128), 256>>>(Wo, bo, out);
}

// round 7
// speedup vs baseline: 2.4132x; 1.0028x over previous
#include <cuda_runtime.h>
#include <cstdint>

#define T_LEN 2048
#define B_SZ  2
#define EMB   512
#define ROWS  4096       // B*T
#define HEADS 8
#define HDIM  64
#define NHASH 2
#define FULLMASK 0xffffffffu

// ---------------------------------------------------------------------------
// Scratch
// ---------------------------------------------------------------------------
__device__ float g_Q[ROWS * EMB];
__device__ float g_K[ROWS * EMB];
__device__ float g_V[ROWS * EMB];
__device__ unsigned char g_qh[NHASH * B_SZ * HEADS * T_LEN];
__device__ unsigned char g_kh[NHASH * B_SZ * HEADS * T_LEN];
__device__ float g_att[NHASH][ROWS * EMB];
__device__ int g_qstart[32][65];
__device__ int g_kstart[32][65];
__device__ unsigned short g_qlist[32 * T_LEN];
__device__ unsigned short g_klist[32 * T_LEN];

// ---------------------------------------------------------------------------
// Packed fp32x2 FMA (sm_100+): one issue slot, two IEEE fp32 FMAs.
// ---------------------------------------------------------------------------
__device__ __forceinline__ float2 ffma2(float2 a, float2 b, float2 c)
{
    unsigned long long ua = *reinterpret_cast<unsigned long long*>(&a);
    unsigned long long ub = *reinterpret_cast<unsigned long long*>(&b);
    unsigned long long uc = *reinterpret_cast<unsigned long long*>(&c);
    unsigned long long ud;
    asm("fma.rn.f32x2 %0, %1, %2, %3;" : "=l"(ud) : "l"(ua), "l"(ub), "l"(uc));
    return *reinterpret_cast<float2*>(&ud);
}

// Layout constants for the big GEMMs (128x128 tile, BK=16, 256 threads).
// A stored DUPLICATED in smem: As2[k][2r]=As2[k][2r+1]=A[row r].
// Thread (tx,ty): rows ty*8+i (i<8), col pairs {p*32+tx*2, +1} (p<4).
#define AS2_STRIDE 258
#define BSX_STRIDE 132
#define QKV_SMEM ((2 * 16 * AS2_STRIDE + 2 * 16 * BSX_STRIDE) * 4)

__device__ __forceinline__ void tile_fma2(const float* __restrict__ A2,
                                          const float* __restrict__ Bx,
                                          float2 acc[8][4], int tx, int ty)
{
#pragma unroll
    for (int k = 0; k < 16; k++) {
        const float* ar = A2 + k * AS2_STRIDE;
        const float* br = Bx + k * BSX_STRIDE;
        float2 avd[8], bv2[4];
#pragma unroll
        for (int i = 0; i < 8; i++)
            avd[i] = *reinterpret_cast<const float2*>(ar + 2 * (ty * 8 + i));
#pragma unroll
        for (int p = 0; p < 4; p++)
            bv2[p] = *reinterpret_cast<const float2*>(br + p * 32 + tx * 2);
#pragma unroll
        for (int i = 0; i < 8; i++)
#pragma unroll
            for (int p = 0; p < 4; p++)
                acc[i][p] = ffma2(avd[i], bv2[p], acc[i][p]);
    }
}

// ---------------------------------------------------------------------------
// Kernel 1: fused QKV projection, double-buffered, f32x2 microkernel.
// ---------------------------------------------------------------------------
__global__ __launch_bounds__(256, 2) void gemm_qkv(
    const float* __restrict__ Xq, const float* __restrict__ Xk, const float* __restrict__ Xv,
    const float* __restrict__ Wq, const float* __restrict__ Wk, const float* __restrict__ Wv,
    const float* __restrict__ bq, const float* __restrict__ bk, const float* __restrict__ bv)
{
    extern __shared__ float sm[];
    float* A2 = sm;                         // [2][16][AS2_STRIDE]
    float* Bx = sm + 2 * 16 * AS2_STRIDE;   // [2][16][BSX_STRIDE]

    const int tid = threadIdx.x;
    const int bn = blockIdx.x;
    const int bm = blockIdx.y;
    const int z  = blockIdx.z;
    const int tx = tid & 15, ty = tid >> 4;

    const float* X = (z == 0) ? Xq : (z == 1) ? Xk : Xv;
    const float* W = (z == 0) ? Wq : (z == 1) ? Wk : Wv;
    const float* bias = (z == 0) ? bq : (z == 1) ? bk : bv;
    float* outp = (z == 0) ? g_Q : (z == 1) ? g_K : g_V;

    const int rr = tid >> 1;           // 0..127 staged row
    const int kb = (tid & 1) * 8;      // k-slot base 0 or 8
    const int r = bm * 128 + rr;
    const int src = (r & 1) * T_LEN + (r >> 1);
    const float* Aptr = X + (size_t)src * EMB + kb;
    const float* Bptr = W + (size_t)(bn * 128 + rr) * EMB + kb;

    float2 acc[8][4];
#pragma unroll
    for (int i = 0; i < 8; i++)
#pragma unroll
        for (int p = 0; p < 4; p++) acc[i][p] = make_float2(0.f, 0.f);

    float4 ra0 = *reinterpret_cast<const float4*>(Aptr);
    float4 ra1 = *reinterpret_cast<const float4*>(Aptr + 4);
    float4 rb0 = *reinterpret_cast<const float4*>(Bptr);
    float4 rb1 = *reinterpret_cast<const float4*>(Bptr + 4);

    {
        float va[8] = {ra0.x, ra0.y, ra0.z, ra0.w, ra1.x, ra1.y, ra1.z, ra1.w};
        float vb[8] = {rb0.x, rb0.y, rb0.z, rb0.w, rb1.x, rb1.y, rb1.z, rb1.w};
#pragma unroll
        for (int c = 0; c < 8; c++) {
            float* pa = A2 + (kb + c) * AS2_STRIDE + 2 * rr;
            pa[0] = va[c]; pa[1] = va[c];
            Bx[(kb + c) * BSX_STRIDE + rr] = vb[c];
        }
    }
    __syncthreads();

    const int NS = EMB / 16;
    for (int s = 0; s < NS; s++) {
        const int cur = s & 1;
        if (s + 1 < NS) {
            ra0 = *reinterpret_cast<const float4*>(Aptr + (s + 1) * 16);
            ra1 = *reinterpret_cast<const float4*>(Aptr + (s + 1) * 16 + 4);
            rb0 = *reinterpret_cast<const float4*>(Bptr + (s + 1) * 16);
            rb1 = *reinterpret_cast<const float4*>(Bptr + (s + 1) * 16 + 4);
        }
        tile_fma2(A2 + cur * 16 * AS2_STRIDE, Bx + cur * 16 * BSX_STRIDE, acc, tx, ty);
        if (s + 1 < NS) {
            __syncthreads();
            const int nxt = cur ^ 1;
            float va[8] = {ra0.x, ra0.y, ra0.z, ra0.w, ra1.x, ra1.y, ra1.z, ra1.w};
            float vb[8] = {rb0.x, rb0.y, rb0.z, rb0.w, rb1.x, rb1.y, rb1.z, rb1.w};
#pragma unroll
            for (int c = 0; c < 8; c++) {
                float* pa = A2 + (nxt * 16 + kb + c) * AS2_STRIDE + 2 * rr;
                pa[0] = va[c]; pa[1] = va[c];
                Bx[(nxt * 16 + kb + c) * BSX_STRIDE + rr] = vb[c];
            }
            __syncthreads();
        }
    }

    float2 bb2[4];
#pragma unroll
    for (int p = 0; p < 4; p++)
        bb2[p] = *reinterpret_cast<const float2*>(bias + bn * 128 + p * 32 + tx * 2);
#pragma unroll
    for (int i = 0; i < 8; i++) {
        int ro = bm * 128 + ty * 8 + i;
        float* op = outp + (size_t)ro * EMB + bn * 128;
#pragma unroll
        for (int p = 0; p < 4; p++) {
            float2 v = acc[i][p];
            v.x += bb2[p].x; v.y += bb2[p].y;
            *reinterpret_cast<float2*>(op + p * 32 + tx * 2) = v;
        }
    }
}

// ---------------------------------------------------------------------------
// Kernel 2: LSH hashing GEMM (64x128 tile), f32x2 + fused argmax.
// Thread (tx,ty): rows ty*4+i, col pairs {p*32+tx*2,+1}; cols 0..63 = hash0,
// 64..127 = hash1 (p<2 vs p>=2).
// ---------------------------------------------------------------------------
__global__ __launch_bounds__(256) void hash_gemm(const float* __restrict__ lshW,
                                                 const float* __restrict__ lshb)
{
    __shared__ float As2h[16][130];
    __shared__ float Bsh[16][132];
    const int tid = threadIdx.x;
    const int bm = blockIdx.x;        // 0..511
    const int tensor = blockIdx.y;    // 0 = Q, 1 = K
    const int tx = tid & 15, ty = tid >> 4;

    const float* A = tensor ? g_K : g_Q;
    unsigned char* dst = tensor ? g_kh : g_qh;

    float2 acc[4][4];
#pragma unroll
    for (int i = 0; i < 4; i++)
#pragma unroll
        for (int p = 0; p < 4; p++) acc[i][p] = make_float2(0.f, 0.f);

    for (int kk = 0; kk < 64; kk += 16) {
        {
            int arr = tid >> 2, ak4 = tid & 3;
            float4 a = *reinterpret_cast<const float4*>(A + (size_t)(bm * 64 + arr) * 64 + kk + ak4 * 4);
            float va[4] = {a.x, a.y, a.z, a.w};
#pragma unroll
            for (int c = 0; c < 4; c++) {
                As2h[ak4 * 4 + c][2 * arr] = va[c];
                As2h[ak4 * 4 + c][2 * arr + 1] = va[c];
            }
        }
#pragma unroll
        for (int i = 0; i < 2; i++) {
            int idx = tid * 2 + i;
            int rr = idx >> 2, bk4 = idx & 3;
            float4 b = *reinterpret_cast<const float4*>(lshW + (size_t)rr * 64 + kk + bk4 * 4);
            Bsh[bk4 * 4 + 0][rr] = b.x; Bsh[bk4 * 4 + 1][rr] = b.y;
            Bsh[bk4 * 4 + 2][rr] = b.z; Bsh[bk4 * 4 + 3][rr] = b.w;
        }
        __syncthreads();
#pragma unroll
        for (int k = 0; k < 16; k++) {
            float2 avd[4], bv2[4];
#pragma unroll
            for (int i = 0; i < 4; i++)
                avd[i] = *reinterpret_cast<const float2*>(&As2h[k][2 * (ty * 4 + i)]);
#pragma unroll
            for (int p = 0; p < 4; p++)
                bv2[p] = *reinterpret_cast<const float2*>(&Bsh[k][p * 32 + tx * 2]);
#pragma unroll
            for (int i = 0; i < 4; i++)
#pragma unroll
                for (int p = 0; p < 4; p++)
                    acc[i][p] = ffma2(avd[i], bv2[p], acc[i][p]);
        }
        __syncthreads();
    }

    float2 bb2[4];
#pragma unroll
    for (int p = 0; p < 4; p++)
        bb2[p] = *reinterpret_cast<const float2*>(lshb + p * 32 + tx * 2);

#pragma unroll
    for (int i = 0; i < 4; i++) {
        const int m  = bm * 64 + ty * 4 + i;
        const int r  = m >> 3, h = m & 7;
        const int nb = r >> 11, nt = r & 2047;
#pragma unroll
        for (int hh = 0; hh < 2; hh++) {
            // candidates from pairs p = 2*hh, 2*hh+1, local d ascending
            float2 c0 = acc[i][2 * hh];     // d = tx*2, tx*2+1
            float2 c1 = acc[i][2 * hh + 1]; // d = 32+tx*2, 33+tx*2
            c0.x += bb2[2 * hh].x;     c0.y += bb2[2 * hh].y;
            c1.x += bb2[2 * hh + 1].x; c1.y += bb2[2 * hh + 1].y;
            float bvv = c0.x; int bi = tx * 2;
            if (c0.y > bvv) { bvv = c0.y; bi = tx * 2 + 1; }
            if (c1.x > bvv) { bvv = c1.x; bi = 32 + tx * 2; }
            if (c1.y > bvv) { bvv = c1.y; bi = 33 + tx * 2; }
#pragma unroll
            for (int off = 1; off < 16; off <<= 1) {
                float ov = __shfl_xor_sync(FULLMASK, bvv, off);
                int   oi = __shfl_xor_sync(FULLMASK, bi, off);
                if (ov > bvv || (ov == bvv && oi < bi)) { bvv = ov; bi = oi; }
            }
            if (tx == 0)
                dst[((hh * B_SZ + nb) * HEADS + h) * T_LEN + nt] = (unsigned char)bi;
        }
    }
}

// ---------------------------------------------------------------------------
// Kernel 3: bucketize
// ---------------------------------------------------------------------------
__global__ __launch_bounds__(256) void bucketize_kernel()
{
    __shared__ int cnt[2][64];
    __shared__ int off[2][64];
    const int combo = blockIdx.x;
    const int tid = threadIdx.x;

    for (int i = tid; i < 128; i += 256) cnt[i >> 6][i & 63] = 0;
    __syncthreads();

    const unsigned char* qh = g_qh + combo * T_LEN;
    const unsigned char* kh = g_kh + combo * T_LEN;
    for (int i = tid; i < T_LEN; i += 256) {
        atomicAdd(&cnt[0][qh[i]], 1);
        atomicAdd(&cnt[1][kh[i]], 1);
    }
    __syncthreads();

    if (tid == 0) {
        int s = 0;
        for (int j = 0; j < 64; j++) { g_qstart[combo][j] = s; off[0][j] = s; s += cnt[0][j]; }
        g_qstart[combo][64] = s;
    }
    if (tid == 32) {
        int s = 0;
        for (int j = 0; j < 64; j++) { g_kstart[combo][j] = s; off[1][j] = s; s += cnt[1][j]; }
        g_kstart[combo][64] = s;
    }
    __syncthreads();

    for (int i = tid; i < T_LEN; i += 256) {
        int p = atomicAdd(&off[0][qh[i]], 1);
        g_qlist[combo * T_LEN + p] = (unsigned short)i;
        p = atomicAdd(&off[1][kh[i]], 1);
        g_klist[combo * T_LEN + p] = (unsigned short)i;
    }
}

// ---------------------------------------------------------------------------
// Kernel 4: per-bucket dense tiled attention (flash-style, as round 5).
// ---------------------------------------------------------------------------
#define AST 65
#define ATT_SMEM (4 * 64 * AST * 4 + 64 * 4)

__global__ __launch_bounds__(256) void attn_bucket_kernel()
{
    extern __shared__ float sm[];
    float* qsh = sm;
    float* ksh = sm + 64 * AST;
    float* vsh = sm + 2 * 64 * AST;
    float* psh = sm + 3 * 64 * AST;
    int*   qid = (int*)(sm + 4 * 64 * AST);

    const int bucket = blockIdx.x;
    const int combo  = blockIdx.y;
    const int hash = combo >> 4;
    const int b    = (combo >> 3) & 1;
    const int h    = combo & 7;
    const int tid  = threadIdx.x;
    const int tx = tid & 15, ty = tid >> 4;

    const int qs = g_qstart[combo][bucket];
    const int nq = g_qstart[combo][bucket + 1] - qs;
    if (nq == 0) return;
    const int ks = g_kstart[combo][bucket];
    const int kn = g_kstart[combo][bucket + 1] - ks;

    const unsigned short* qlist = g_qlist + combo * T_LEN;
    const unsigned short* klist = g_klist + combo * T_LEN;

    float* Op = g_att[hash] + (size_t)b * T_LEN * EMB + h * HDIM;

    if (bucket >= 32 || kn == 0) {
        for (int idx = tid; idx < nq * 16; idx += 256) {
            int qi = idx >> 4, sl = idx & 15;
            int t = qlist[qs + qi];
            *reinterpret_cast<float4*>(Op + (size_t)t * EMB + sl * 4) =
                make_float4(0.f, 0.f, 0.f, 0.f);
        }
        return;
    }

    const float* Qp = g_Q + (size_t)b * T_LEN * EMB + h * HDIM;
    const float* Kp = g_K + (size_t)b * T_LEN * EMB + h * HDIM;
    const float* Vp = g_V + (size_t)b * T_LEN * EMB + h * HDIM;

    for (int q0 = 0; q0 < nq; q0 += 64) {
        const int cq = min(64, nq - q0);
        __syncthreads();
        for (int task = tid; task < 64 * 16; task += 256) {
            int row = task >> 4, slot = task & 15;
            if (row < cq) {
                int t = qlist[qs + q0 + row];
                if (slot == 0) qid[row] = t;
                float4 v4 = *reinterpret_cast<const float4*>(Qp + (size_t)t * EMB + slot * 4);
                float* d = &qsh[row * AST + slot * 4];
                d[0] = v4.x; d[1] = v4.y; d[2] = v4.z; d[3] = v4.w;
            }
        }
        __syncthreads();

        float m[4], l[4], o[4][4];
#pragma unroll
        for (int i = 0; i < 4; i++) {
            m[i] = -INFINITY; l[i] = 0.f;
#pragma unroll
            for (int d = 0; d < 4; d++) o[i][d] = 0.f;
        }

        for (int k0 = 0; k0 < kn; k0 += 64) {
            const int cnk = min(64, kn - k0);
            __syncthreads();
            for (int task = tid; task < 64 * 16; task += 256) {
                int row = task >> 4, slot = task & 15;
                float* dk = &ksh[row * AST + slot * 4];
                float* dv = &vsh[row * AST + slot * 4];
                if (row < cnk) {
                    int t = klist[ks + k0 + row];
                    float4 k4 = *reinterpret_cast<const float4*>(Kp + (size_t)t * EMB + slot * 4);
                    dk[0] = k4.x; dk[1] = k4.y; dk[2] = k4.z; dk[3] = k4.w;
                    float4 v4 = *reinterpret_cast<const float4*>(Vp + (size_t)t * EMB + slot * 4);
                    dv[0] = v4.x; dv[1] = v4.y; dv[2] = v4.z; dv[3] = v4.w;
                } else {
                    dv[0] = 0.f; dv[1] = 0.f; dv[2] = 0.f; dv[3] = 0.f;
                }
            }
            __syncthreads();

            float s4[4][4];
#pragma unroll
            for (int i = 0; i < 4; i++)
#pragma unroll
                for (int j = 0; j < 4; j++) s4[i][j] = 0.f;
#pragma unroll
            for (int k = 0; k < 64; k++) {
                float av[4], bv[4];
#pragma unroll
                for (int i = 0; i < 4; i++) av[i] = qsh[(ty * 4 + i) * AST + k];
#pragma unroll
                for (int j = 0; j < 4; j++) bv[j] = ksh[(tx * 4 + j) * AST + k];
#pragma unroll
                for (int i = 0; i < 4; i++)
#pragma unroll
                    for (int j = 0; j < 4; j++) s4[i][j] += av[i] * bv[j];
            }
#pragma unroll
            for (int i = 0; i < 4; i++)
#pragma unroll
                for (int j = 0; j < 4; j++)
                    s4[i][j] = (tx * 4 + j < cnk) ? s4[i][j] * 0.125f : -INFINITY;

            float cm[4];
#pragma unroll
            for (int i = 0; i < 4; i++) {
                cm[i] = fmaxf(fmaxf(s4[i][0], s4[i][1]), fmaxf(s4[i][2], s4[i][3]));
#pragma unroll
                for (int off = 1; off < 16; off <<= 1)
                    cm[i] = fmaxf(cm[i], __shfl_xor_sync(FULLMASK, cm[i], off));
            }
            float corr[4], ps[4];
#pragma unroll
            for (int i = 0; i < 4; i++) {
                float mn = fmaxf(m[i], cm[i]);
                corr[i] = __expf(m[i] - mn);
                m[i] = mn;
                ps[i] = 0.f;
#pragma unroll
                for (int j = 0; j < 4; j++) {
                    float w = __expf(s4[i][j] - mn);
                    s4[i][j] = w;
                    ps[i] += w;
                }
#pragma unroll
                for (int off = 1; off < 16; off <<= 1)
                    ps[i] += __shfl_xor_sync(FULLMASK, ps[i], off);
                l[i] = l[i] * corr[i] + ps[i];
#pragma unroll
                for (int d = 0; d < 4; d++) o[i][d] *= corr[i];
            }
#pragma unroll
            for (int i = 0; i < 4; i++)
#pragma unroll
                for (int j = 0; j < 4; j++)
                    psh[(ty * 4 + i) * AST + tx * 4 + j] = s4[i][j];
            __syncthreads();
#pragma unroll 8
            for (int j = 0; j < 64; j++) {
                float pv[4], vv[4];
#pragma unroll
                for (int i = 0; i < 4; i++) pv[i] = psh[(ty * 4 + i) * AST + j];
#pragma unroll
                for (int d = 0; d < 4; d++) vv[d] = vsh[j * AST + tx * 4 + d];
#pragma unroll
                for (int i = 0; i < 4; i++)
#pragma unroll
                    for (int d = 0; d < 4; d++) o[i][d] += pv[i] * vv[d];
            }
        }

#pragma unroll
        for (int i = 0; i < 4; i++) {
            int row = ty * 4 + i;
            if (row < cq) {
                float inv = 1.f / l[i];
                int t = qid[row];
                float4 v;
                v.x = o[i][0] * inv; v.y = o[i][1] * inv;
                v.z = o[i][2] * inv; v.w = o[i][3] * inv;
                *reinterpret_cast<float4*>(Op + (size_t)t * EMB + tx * 4) = v;
            }
        }
    }
}

// ---------------------------------------------------------------------------
// Kernel 5: output projection, f32x2, fused hash-average + transpose store.
// ---------------------------------------------------------------------------
__global__ __launch_bounds__(256, 2) void gemm_out(const float* __restrict__ W,
                                                   const float* __restrict__ bias,
                                                   float* __restrict__ out)
{
    extern __shared__ float sm[];
    float* A2 = sm;
    float* Bx = sm + 2 * 16 * AS2_STRIDE;

    const int tid = threadIdx.x;
    const int bn = blockIdx.x;
    const int bm = blockIdx.y;
    const int tx = tid & 15, ty = tid >> 4;

    const int rr = tid >> 1;
    const int kb = (tid & 1) * 8;
    const int r = bm * 128 + rr;
    const float* A0 = &g_att[0][(size_t)r * EMB + kb];
    const float* A1 = &g_att[1][(size_t)r * EMB + kb];
    const float* Bptr = W + (size_t)(bn * 128 + rr) * EMB + kb;

    float2 acc[8][4];
#pragma unroll
    for (int i = 0; i < 8; i++)
#pragma unroll
        for (int p = 0; p < 4; p++) acc[i][p] = make_float2(0.f, 0.f);

    float4 ra0, ra1, rb0, rb1;
    {
        float4 x0 = *reinterpret_cast<const float4*>(A0);
        float4 y0 = *reinterpret_cast<const float4*>(A1);
        float4 x1 = *reinterpret_cast<const float4*>(A0 + 4);
        float4 y1 = *reinterpret_cast<const float4*>(A1 + 4);
        ra0 = make_float4(0.5f * (x0.x + y0.x), 0.5f * (x0.y + y0.y), 0.5f * (x0.z + y0.z), 0.5f * (x0.w + y0.w));
        ra1 = make_float4(0.5f * (x1.x + y1.x), 0.5f * (x1.y + y1.y), 0.5f * (x1.z + y1.z), 0.5f * (x1.w + y1.w));
        rb0 = *reinterpret_cast<const float4*>(Bptr);
        rb1 = *reinterpret_cast<const float4*>(Bptr + 4);
        float va[8] = {ra0.x, ra0.y, ra0.z, ra0.w, ra1.x, ra1.y, ra1.z, ra1.w};
        float vb[8] = {rb0.x, rb0.y, rb0.z, rb0.w, rb1.x, rb1.y, rb1.z, rb1.w};
#pragma unroll
        for (int c = 0; c < 8; c++) {
            float* pa = A2 + (kb + c) * AS2_STRIDE + 2 * rr;
            pa[0] = va[c]; pa[1] = va[c];
            Bx[(kb + c) * BSX_STRIDE + rr] = vb[c];
        }
    }
    __syncthreads();

    const int NS = EMB / 16;
    for (int s = 0; s < NS; s++) {
        const int cur = s & 1;
        if (s + 1 < NS) {
            const int o = (s + 1) * 16;
            float4 x0 = *reinterpret_cast<const float4*>(A0 + o);
            float4 y0 = *reinterpret_cast<const float4*>(A1 + o);
            float4 x1 = *reinterpret_cast<const float4*>(A0 + o + 4);
            float4 y1 = *reinterpret_cast<const float4*>(A1 + o + 4);
            ra0 = make_float4(0.5f * (x0.x + y0.x), 0.5f * (x0.y + y0.y), 0.5f * (x0.z + y0.z), 0.5f * (x0.w + y0.w));
            ra1 = make_float4(0.5f * (x1.x + y1.x), 0.5f * (x1.y + y1.y), 0.5f * (x1.z + y1.z), 0.5f * (x1.w + y1.w));
            rb0 = *reinterpret_cast<const float4*>(Bptr + o);
            rb1 = *reinterpret_cast<const float4*>(Bptr + o + 4);
        }
        tile_fma2(A2 + cur * 16 * AS2_STRIDE, Bx + cur * 16 * BSX_STRIDE, acc, tx, ty);
        if (s + 1 < NS) {
            __syncthreads();
            const int nxt = cur ^ 1;
            float va[8] = {ra0.x, ra0.y, ra0.z, ra0.w, ra1.x, ra1.y, ra1.z, ra1.w};
            float vb[8] = {rb0.x, rb0.y, rb0.z, rb0.w, rb1.x, rb1.y, rb1.z, rb1.w};
#pragma unroll
            for (int c = 0; c < 8; c++) {
                float* pa = A2 + (nxt * 16 + kb + c) * AS2_STRIDE + 2 * rr;
                pa[0] = va[c]; pa[1] = va[c];
                Bx[(nxt * 16 + kb + c) * BSX_STRIDE + rr] = vb[c];
            }
            __syncthreads();
        }
    }

    float2 bb2[4];
#pragma unroll
    for (int p = 0; p < 4; p++)
        bb2[p] = *reinterpret_cast<const float2*>(bias + bn * 128 + p * 32 + tx * 2);
#pragma unroll
    for (int i = 0; i < 8; i++) {
        int ro = bm * 128 + ty * 8 + i;           // (nb, nt) flat
        int g = (ro & 2047) * B_SZ + (ro >> 11);  // -> (nt, nb) flat
        float* op = out + (size_t)g * EMB + bn * 128;
#pragma unroll
        for (int p = 0; p < 4; p++) {
            float2 v = acc[i][p];
            v.x += bb2[p].x; v.y += bb2[p].y;
            *reinterpret_cast<float2*>(op + p * 32 + tx * 2) = v;
        }
    }
}

// ---------------------------------------------------------------------------
extern "C" void kernel_launch(void* const* d_in, const int* in_sizes, int n_in,
                              void* d_out, int out_size)
{
    (void)in_sizes; (void)n_in; (void)out_size;
    const float* query = (const float*)d_in[0];
    const float* key   = (const float*)d_in[1];
    const float* value = (const float*)d_in[2];
    const float* Wq = (const float*)d_in[3];
    const float* bq = (const float*)d_in[4];
    const float* Wk = (const float*)d_in[5];
    const float* bk = (const float*)d_in[6];
    const float* Wv = (const float*)d_in[7];
    const float* bv = (const float*)d_in[8];
    const float* Wo = (const float*)d_in[9];
    const float* bo = (const float*)d_in[10];
    const float* lshW = (const float*)d_in[11];
    const float* lshb = (const float*)d_in[12];
    float* out = (float*)d_out;

    cudaFuncSetAttribute(gemm_qkv, cudaFuncAttributeMaxDynamicSharedMemorySize, QKV_SMEM);
    cudaFuncSetAttribute(gemm_out, cudaFuncAttributeMaxDynamicSharedMemorySize, QKV_SMEM);
    cudaFuncSetAttribute(attn_bucket_kernel, cudaFuncAttributeMaxDynamicSharedMemorySize, ATT_SMEM);

    gemm_qkv<<<dim3(EMB / 128, ROWS / 128, 3), 256, QKV_SMEM>>>(query, key, value,
                                                                Wq, Wk, Wv, bq, bk, bv);
    hash_gemm<<<dim3(512, 2), 256>>>(lshW, lshb);
    bucketize_kernel<<<32, 256>>>();
    attn_bucket_kernel<<<dim3(64, 32), 256, ATT_SMEM>>>();
    gemm_out<<<dim3(EMB / 128, ROWS / 128), 256, QKV_SMEM>>>(Wo, bo, out);
}